// round 4
// baseline (speedup 1.0000x reference)
#include <cuda_runtime.h>

typedef unsigned long long ull;
#define PLANE 4096
#define KTOT  2304

__device__ float g_om[8 * 27 * PLANE];
__device__ float g_y [8 * 256 * PLANE];
__device__ float g_a [256];
__device__ float g_bsh[256];

__device__ __forceinline__ ull fma2(ull a, ull b, ull c) {
    ull d; asm("fma.rn.f32x2 %0, %1, %2, %3;" : "=l"(d) : "l"(a), "l"(b), "l"(c)); return d;
}
__device__ __forceinline__ ull pack2(float lo, float hi) {
    ull v; asm("mov.b64 %0, {%1, %2};" : "=l"(v) : "f"(lo), "f"(hi)); return v;
}
__device__ __forceinline__ float2 unpack2(ull v) {
    float2 f; asm("mov.b64 {%0, %1}, %2;" : "=f"(f.x), "=f"(f.y) : "l"(v)); return f;
}

// ============ Kernel 1: offset conv (27ch 3x3) ============
__global__ void __launch_bounds__(128) offset_conv(const float* __restrict__ x,
                                                   const float* __restrict__ woff,
                                                   const float* __restrict__ boff) {
    __shared__ float sw[27 * 32 * 12];
    const int tid = threadIdx.x;
    const int b = blockIdx.x >> 5;
    const int h = ((blockIdx.x & 31) << 1) + (tid >> 6);
    const int w = tid & 63;

    ull acc2[27]; float acc1[27];
#pragma unroll
    for (int oc = 0; oc < 27; oc++) { acc2[oc] = 0ULL; acc1[oc] = 0.f; }

    for (int c0 = 0; c0 < 256; c0 += 32) {
        __syncthreads();
        for (int i = tid; i < 27 * 32 * 9; i += 128) {
            int oc = i / 288, rem = i - oc * 288;
            int cl = rem / 9, j = rem - cl * 9;
            sw[(oc * 32 + cl) * 12 + j] = __ldg(&woff[(oc * 256 + c0 + cl) * 9 + j]);
        }
        __syncthreads();
        for (int cl = 0; cl < 32; cl++) {
            const float* xc = x + ((size_t)(b * 256 + c0 + cl) << 12);
            float v[9];
#pragma unroll
            for (int a = 0; a < 3; a++)
#pragma unroll
                for (int e = 0; e < 3; e++) {
                    int hh = h + a - 1, ww = w + e - 1;
                    bool ok = (hh >= 0) & (hh < 64) & (ww >= 0) & (ww < 64);
                    v[a * 3 + e] = ok ? __ldg(xc + hh * 64 + ww) : 0.f;
                }
            ull p0 = pack2(v[0], v[1]), p1 = pack2(v[2], v[3]);
            ull p2 = pack2(v[4], v[5]), p3 = pack2(v[6], v[7]);
            float v8 = v[8];
            const float* wb = sw + cl * 12;
#pragma unroll
            for (int oc = 0; oc < 27; oc++) {
                const float* wr = wb + oc * 384;
                ulonglong2 w01 = *(const ulonglong2*)(wr);
                ulonglong2 w23 = *(const ulonglong2*)(wr + 4);
                acc2[oc] = fma2(p0, w01.x, acc2[oc]);
                acc2[oc] = fma2(p1, w01.y, acc2[oc]);
                acc2[oc] = fma2(p2, w23.x, acc2[oc]);
                acc2[oc] = fma2(p3, w23.y, acc2[oc]);
                acc1[oc] = fmaf(v8, wr[8], acc1[oc]);
            }
        }
    }
#pragma unroll
    for (int oc = 0; oc < 27; oc++) {
        float2 f = unpack2(acc2[oc]);
        g_om[((size_t)(b * 27 + oc) << 12) + h * 64 + w] = f.x + f.y + acc1[oc] + __ldg(boff + oc);
    }
}

// ============ Kernel 2: deformable gather + main GEMM ============
#define SM_BS   18432
#define SM_COEF 55296
#define SM_IDX  64512
#define SMEM2   73728

__global__ void __launch_bounds__(256, 2) deform_gemm(const float* __restrict__ x,
                                                      const float* __restrict__ weight,
                                                      const float* __restrict__ bias) {
    extern __shared__ char smem[];
    float2* As2  = (float2*)(smem);            // [36][64] pre-duplicated
    float*  Bs   = (float*)(smem + SM_BS);     // [36][256]
    float*  scoef = (float*)(smem + SM_COEF);  // [4][9*64]
    int*    sidx  = (int*)(smem + SM_IDX);

    const int tid = threadIdx.x;
    const int b = blockIdx.x >> 6;
    const int h = blockIdx.x & 63;
    const int tx = tid & 15;
    const int ty = tid >> 4;

    // prologue: bilinear coefs per (tap, pixel); mask & validity folded in
    for (int i = tid; i < 576; i += 256) {
        int k = i >> 6, px = i & 63;
        const float* omb = g_om + ((size_t)(b * 27) << 12) + h * 64 + px;
        float offh = omb[(size_t)(2 * k) << 12];
        float offw = omb[(size_t)(2 * k + 1) << 12];
        float mv   = omb[(size_t)(18 + k) << 12];
        float mask = 1.f / (1.f + __expf(-mv));
        int kh = k / 3, kw = k - kh * 3;
        float ph = (float)(h + kh - 1) + offh;
        float pw = (float)(px + kw - 1) + offw;
        float fh0 = floorf(ph), fw0 = floorf(pw);
        int h0 = (int)fh0, w0 = (int)fw0;
        float lh = ph - fh0, lw = pw - fw0;
        float hh = 1.f - lh, hw = 1.f - lw;
        bool vh0 = (h0 >= 0) & (h0 < 64), vh1 = (h0 >= -1) & (h0 < 63);
        bool vw0 = (w0 >= 0) & (w0 < 64), vw1 = (w0 >= -1) & (w0 < 63);
        int ch0 = min(max(h0, 0), 63), ch1 = min(max(h0 + 1, 0), 63);
        int cw0 = min(max(w0, 0), 63), cw1 = min(max(w0 + 1, 0), 63);
        int base = k * 64 + px;
        scoef[base]        = (vh0 & vw0) ? hh * hw * mask : 0.f;
        scoef[base + 576]  = (vh0 & vw1) ? hh * lw * mask : 0.f;
        scoef[base + 1152] = (vh1 & vw0) ? lh * hw * mask : 0.f;
        scoef[base + 1728] = (vh1 & vw1) ? lh * lw * mask : 0.f;
        sidx[base]        = ch0 * 64 + cw0;
        sidx[base + 576]  = ch0 * 64 + cw1;
        sidx[base + 1152] = ch1 * 64 + cw0;
        sidx[base + 1728] = ch1 * 64 + cw1;
    }

    ull acc[4][8];
#pragma unroll
    for (int p = 0; p < 4; p++)
#pragma unroll
        for (int j = 0; j < 8; j++) acc[p][j] = 0ULL;

    const float* xb = x + ((size_t)(b * 256) << 12);
    const int tw = tid >> 6, pxs = tid & 63;

    for (int cc = 0; cc < 64; cc++) {
        __syncthreads();
        // stage B: this thread owns oc = tid
        {
            const float* wrow = weight + (size_t)tid * KTOT + cc * 36;
#pragma unroll
            for (int j4 = 0; j4 < 9; j4++) {
                float4 wv = *(const float4*)(wrow + j4 * 4);
                float* d = Bs + (j4 * 4) * 256 + tid;
                d[0] = wv.x; d[256] = wv.y; d[512] = wv.z; d[768] = wv.w;
            }
        }
        // stage A: bilinear gather, store (s,s)
#pragma unroll
        for (int r = 0; r < 9; r++) {
            int t = r * 4 + tw;
            int cq = t / 9, k = t - cq * 9;
            const float* xc = xb + ((size_t)(cc * 4 + cq) << 12);
            int kb = k * 64 + pxs;
            float s;
            s  = scoef[kb]        * __ldg(xc + sidx[kb]);
            s += scoef[kb + 576]  * __ldg(xc + sidx[kb + 576]);
            s += scoef[kb + 1152] * __ldg(xc + sidx[kb + 1152]);
            s += scoef[kb + 1728] * __ldg(xc + sidx[kb + 1728]);
            As2[t * 64 + pxs] = make_float2(s, s);
        }
        __syncthreads();
        // GEMM over 36-wide chunk, all f32x2
        const float2* pa = As2 + tx * 4;
        const float*  pb = Bs + ty * 4;
#pragma unroll 4
        for (int t = 0; t < 36; t++) {
            ulonglong2 a01 = *(const ulonglong2*)(pa + t * 64);
            ulonglong2 a23 = *(const ulonglong2*)(pa + t * 64 + 2);
            ull a2[4] = {a01.x, a01.y, a23.x, a23.y};
            ull b2[8];
#pragma unroll
            for (int j2 = 0; j2 < 4; j2++) {
                ulonglong2 bv = *(const ulonglong2*)(pb + t * 256 + j2 * 64);
                b2[2 * j2] = bv.x; b2[2 * j2 + 1] = bv.y;
            }
#pragma unroll
            for (int p = 0; p < 4; p++)
#pragma unroll
                for (int j = 0; j < 8; j++)
                    acc[p][j] = fma2(a2[p], b2[j], acc[p][j]);
        }
    }

    float* yb = g_y + ((size_t)(b * 256) << 12) + h * 64 + tx * 4;
#pragma unroll
    for (int j2 = 0; j2 < 4; j2++)
#pragma unroll
        for (int i2 = 0; i2 < 2; i2++) {
            int oc = ty * 4 + j2 * 64 + i2 * 2;
            int jj = j2 * 2 + i2;
            float2 v0 = unpack2(acc[0][jj]);
            float2 v1 = unpack2(acc[1][jj]);
            float2 v2 = unpack2(acc[2][jj]);
            float2 v3 = unpack2(acc[3][jj]);
            float b0 = __ldg(bias + oc), b1 = __ldg(bias + oc + 1);
            float4 lo = make_float4(v0.x + b0, v1.x + b0, v2.x + b0, v3.x + b0);
            float4 hi = make_float4(v0.y + b1, v1.y + b1, v2.y + b1, v3.y + b1);
            *(float4*)(yb + ((size_t)oc << 12))       = lo;
            *(float4*)(yb + ((size_t)(oc + 1) << 12)) = hi;
        }
}

// ============ Kernel 3: per-channel mean/var -> scale/shift ============
__global__ void __launch_bounds__(256) stats_kernel(const float* __restrict__ gamma,
                                                    const float* __restrict__ beta) {
    __shared__ float ss[256], sq[256];
    const int ch = blockIdx.x, tid = threadIdx.x;
    float s = 0.f, q = 0.f;
    for (int b = 0; b < 8; b++) {
        const float4* y4 = (const float4*)(g_y + ((size_t)(b * 256 + ch) << 12));
#pragma unroll
        for (int r = 0; r < 4; r++) {
            float4 v = y4[r * 256 + tid];
            s += (v.x + v.y) + (v.z + v.w);
            q += v.x * v.x + v.y * v.y + v.z * v.z + v.w * v.w;
        }
    }
    ss[tid] = s; sq[tid] = q;
    __syncthreads();
    for (int o = 128; o > 0; o >>= 1) {
        if (tid < o) { ss[tid] += ss[tid + o]; sq[tid] += sq[tid + o]; }
        __syncthreads();
    }
    if (tid == 0) {
        float mean = ss[0] * (1.f / 32768.f);
        float var  = sq[0] * (1.f / 32768.f) - mean * mean;
        float a = __ldg(gamma + ch) * rsqrtf(var + 1e-5f);
        g_a[ch] = a;
        g_bsh[ch] = __ldg(beta + ch) - mean * a;
    }
}

// ============ Kernel 4: normalize + ReLU ============
__global__ void __launch_bounds__(256) norm_kernel(float* __restrict__ out) {
    int i4 = blockIdx.x * 256 + threadIdx.x;   // float4 index, 2M total
    int ch = (i4 >> 10) & 255;
    float a = g_a[ch], sh = g_bsh[ch];
    float4 v = ((const float4*)g_y)[i4];
    v.x = fmaxf(v.x * a + sh, 0.f);
    v.y = fmaxf(v.y * a + sh, 0.f);
    v.z = fmaxf(v.z * a + sh, 0.f);
    v.w = fmaxf(v.w * a + sh, 0.f);
    ((float4*)out)[i4] = v;
}

extern "C" void kernel_launch(void* const* d_in, const int* in_sizes, int n_in,
                              void* d_out, int out_size) {
    const float* x      = (const float*)d_in[0];
    const float* w_off  = (const float*)d_in[1];
    const float* b_off  = (const float*)d_in[2];
    const float* weight = (const float*)d_in[3];
    const float* bias   = (const float*)d_in[4];
    const float* gamma  = (const float*)d_in[5];
    const float* beta   = (const float*)d_in[6];
    float* out = (float*)d_out;

    static bool attr_set = false;
    if (!attr_set) {
        cudaFuncSetAttribute(deform_gemm, cudaFuncAttributeMaxDynamicSharedMemorySize, SMEM2);
        attr_set = true;
    }

    offset_conv<<<256, 128>>>(x, w_off, b_off);
    deform_gemm<<<512, 256, SMEM2>>>(x, weight, bias);
    stats_kernel<<<256, 256>>>(gamma, beta);
    norm_kernel<<<8192, 256>>>(out);
}

// round 6
// speedup vs baseline: 2.3057x; 2.3057x over previous
#include <cuda_runtime.h>
#include <cuda_bf16.h>
#include <cstdint>

typedef unsigned long long ull;
#define PLANE 4096
#define KTOT  2304

__device__ float g_om[8 * 27 * PLANE];
__device__ float g_y [8 * 256 * PLANE];
__device__ float g_a [256];
__device__ float g_bsh[256];
__device__ __nv_bfloat16 g_whi[256 * KTOT];
__device__ __nv_bfloat16 g_wlo[256 * KTOT];

__device__ __forceinline__ ull fma2(ull a, ull b, ull c) {
    ull d; asm("fma.rn.f32x2 %0, %1, %2, %3;" : "=l"(d) : "l"(a), "l"(b), "l"(c)); return d;
}
__device__ __forceinline__ ull pack2(float lo, float hi) {
    ull v; asm("mov.b64 %0, {%1, %2};" : "=l"(v) : "f"(lo), "f"(hi)); return v;
}
__device__ __forceinline__ float2 unpack2(ull v) {
    float2 f; asm("mov.b64 {%0, %1}, %2;" : "=f"(f.x), "=f"(f.y) : "l"(v)); return f;
}
__device__ __forceinline__ void mma16816(float* d, const uint32_t* a, const uint32_t* b) {
    asm volatile(
        "mma.sync.aligned.m16n8k16.row.col.f32.bf16.bf16.f32 "
        "{%0,%1,%2,%3}, {%4,%5,%6,%7}, {%8,%9}, {%0,%1,%2,%3};"
        : "+f"(d[0]), "+f"(d[1]), "+f"(d[2]), "+f"(d[3])
        : "r"(a[0]), "r"(a[1]), "r"(a[2]), "r"(a[3]), "r"(b[0]), "r"(b[1]));
}

// ============ Kernel 1: offset conv (27ch 3x3) ============
__global__ void __launch_bounds__(128) offset_conv(const float* __restrict__ x,
                                                   const float* __restrict__ woff,
                                                   const float* __restrict__ boff) {
    __shared__ float sw[27 * 32 * 12];
    const int tid = threadIdx.x;
    const int b = blockIdx.x >> 5;
    const int h = ((blockIdx.x & 31) << 1) + (tid >> 6);
    const int w = tid & 63;

    ull acc2[27]; float acc1[27];
#pragma unroll
    for (int oc = 0; oc < 27; oc++) { acc2[oc] = 0ULL; acc1[oc] = 0.f; }

    for (int c0 = 0; c0 < 256; c0 += 32) {
        __syncthreads();
        for (int i = tid; i < 27 * 32 * 9; i += 128) {
            int oc = i / 288, rem = i - oc * 288;
            int cl = rem / 9, j = rem - cl * 9;
            sw[(oc * 32 + cl) * 12 + j] = __ldg(&woff[(oc * 256 + c0 + cl) * 9 + j]);
        }
        __syncthreads();
        for (int cl = 0; cl < 32; cl++) {
            const float* xc = x + ((size_t)(b * 256 + c0 + cl) << 12);
            float v[9];
#pragma unroll
            for (int a = 0; a < 3; a++)
#pragma unroll
                for (int e = 0; e < 3; e++) {
                    int hh = h + a - 1, ww = w + e - 1;
                    bool ok = (hh >= 0) & (hh < 64) & (ww >= 0) & (ww < 64);
                    v[a * 3 + e] = ok ? __ldg(xc + hh * 64 + ww) : 0.f;
                }
            ull p0 = pack2(v[0], v[1]), p1 = pack2(v[2], v[3]);
            ull p2 = pack2(v[4], v[5]), p3 = pack2(v[6], v[7]);
            float v8 = v[8];
            const float* wb = sw + cl * 12;
#pragma unroll
            for (int oc = 0; oc < 27; oc++) {
                const float* wr = wb + oc * 384;
                ulonglong2 w01 = *(const ulonglong2*)(wr);
                ulonglong2 w23 = *(const ulonglong2*)(wr + 4);
                acc2[oc] = fma2(p0, w01.x, acc2[oc]);
                acc2[oc] = fma2(p1, w01.y, acc2[oc]);
                acc2[oc] = fma2(p2, w23.x, acc2[oc]);
                acc2[oc] = fma2(p3, w23.y, acc2[oc]);
                acc1[oc] = fmaf(v8, wr[8], acc1[oc]);
            }
        }
    }
#pragma unroll
    for (int oc = 0; oc < 27; oc++) {
        float2 f = unpack2(acc2[oc]);
        g_om[((size_t)(b * 27 + oc) << 12) + h * 64 + w] = f.x + f.y + acc1[oc] + __ldg(boff + oc);
    }
}

// ============ Kernel 1b: split weight into bf16 hi/lo ============
__global__ void __launch_bounds__(512) convert_w(const float* __restrict__ weight) {
    int i = blockIdx.x * 512 + threadIdx.x;      // 589824 total
    float w = __ldg(weight + i);
    __nv_bfloat16 hi = __float2bfloat16(w);
    float hf = __bfloat162float(hi);
    g_whi[i] = hi;
    g_wlo[i] = __float2bfloat16(w - hf);
}

// ============ Kernel 2: deformable gather + split-bf16 mma.sync GEMM ============
// CTA per (b, h-pair): M=128 px, N=256 oc, K=2304 in 36 chunks of 64.
// Tiles pitch 144 B (36 words) -> conflict-free LDS.32 operand fetch.
#define APITCH_W 36
#define SM_A_HI 0
#define SM_A_LO 18432
#define SM_B_HI 36864
#define SM_B_LO 73728
#define SM_COEF 110592
#define SM_IDX  129024
#define SMEM_TC 138240

__global__ void __launch_bounds__(512, 1) deform_gemm_tc(const float* __restrict__ x,
                                                         const float* __restrict__ bias) {
    extern __shared__ char smem[];
    const int tid = threadIdx.x;
    const int wid = tid >> 5;
    const int lane = tid & 31;
    const int b = blockIdx.x >> 5;
    const int h0 = (blockIdx.x & 31) << 1;

    float4*  coef4 = (float4*)(smem + SM_COEF);
    ushort4* idx4  = (ushort4*)(smem + SM_IDX);
    const uint32_t* AsH = (const uint32_t*)(smem + SM_A_HI);
    const uint32_t* AsL = (const uint32_t*)(smem + SM_A_LO);
    const uint32_t* BsH = (const uint32_t*)(smem + SM_B_HI);
    const uint32_t* BsL = (const uint32_t*)(smem + SM_B_LO);

    // ---- prologue: bilinear coefs per (tap, m)
    for (int i = tid; i < 1152; i += 512) {
        int tap = i >> 7, m = i & 127;
        int r = m >> 6, px = m & 63;
        int h = h0 + r;
        const float* omb = g_om + ((size_t)(b * 27) << 12) + h * 64 + px;
        float offh = omb[(size_t)(2 * tap) << 12];
        float offw = omb[(size_t)(2 * tap + 1) << 12];
        float mv   = omb[(size_t)(18 + tap) << 12];
        float mask = 1.f / (1.f + __expf(-mv));
        int kh = tap / 3, kw = tap - kh * 3;
        float ph = (float)(h + kh - 1) + offh;
        float pw = (float)(px + kw - 1) + offw;
        float fh0 = floorf(ph), fw0 = floorf(pw);
        int hh0 = (int)fh0, ww0 = (int)fw0;
        float lh = ph - fh0, lw = pw - fw0;
        float hh = 1.f - lh, hw = 1.f - lw;
        bool vh0 = (hh0 >= 0) & (hh0 < 64), vh1 = (hh0 >= -1) & (hh0 < 63);
        bool vw0 = (ww0 >= 0) & (ww0 < 64), vw1 = (ww0 >= -1) & (ww0 < 63);
        int ch0 = min(max(hh0, 0), 63), ch1 = min(max(hh0 + 1, 0), 63);
        int cw0 = min(max(ww0, 0), 63), cw1 = min(max(ww0 + 1, 0), 63);
        float4 cf;
        cf.x = (vh0 & vw0) ? hh * hw * mask : 0.f;
        cf.y = (vh0 & vw1) ? hh * lw * mask : 0.f;
        cf.z = (vh1 & vw0) ? lh * hw * mask : 0.f;
        cf.w = (vh1 & vw1) ? lh * lw * mask : 0.f;
        coef4[i] = cf;
        ushort4 ix;
        ix.x = (unsigned short)(ch0 * 64 + cw0);
        ix.y = (unsigned short)(ch0 * 64 + cw1);
        ix.z = (unsigned short)(ch1 * 64 + cw0);
        ix.w = (unsigned short)(ch1 * 64 + cw1);
        idx4[i] = ix;
    }

    const float* xb = x + ((size_t)(b * 256) << 12);
    const int m   = tid & 127;    // gather: M row owned
    const int kb0 = (tid >> 7) << 4;

    const int g = lane >> 2, t = lane & 3;
    const int wm = (wid & 3) << 5;        // warp M origin (0,32,64,96)
    const int wn = (wid >> 2) << 6;       // warp N origin (0,64,128,192)

    float acc[2][8][4];
#pragma unroll
    for (int f = 0; f < 2; f++)
#pragma unroll
        for (int ni = 0; ni < 8; ni++)
#pragma unroll
            for (int e = 0; e < 4; e++) acc[f][ni][e] = 0.f;

    for (int cc = 0; cc < 36; cc++) {
        __syncthreads();
        // ---- stage B hi/lo [256 oc x 64 k], pitch 144B
#pragma unroll
        for (int i = 0; i < 4; i++) {
            int lin = i * 512 + tid;          // 2048 = 256 oc x 8 segs
            int oc = lin >> 3, j = lin & 7;
            size_t gofs = (size_t)oc * KTOT + cc * 64 + j * 8;
            uint4 vh = *(const uint4*)(g_whi + gofs);
            uint4 vl = *(const uint4*)(g_wlo + gofs);
            *(uint4*)(smem + SM_B_HI + oc * 144 + j * 16) = vh;
            *(uint4*)(smem + SM_B_LO + oc * 144 + j * 16) = vl;
        }
        // ---- gather A hi/lo [128 m x 64 k]
#pragma unroll
        for (int gseg = 0; gseg < 2; gseg++) {
            unsigned short hb[8], lb[8];
#pragma unroll
            for (int jj = 0; jj < 8; jj++) {
                int kl = kb0 + gseg * 8 + jj;
                int kg = cc * 64 + kl;
                int c  = kg / 9;
                int tap = kg - c * 9;
                float4  cf = coef4[tap * 128 + m];
                ushort4 ix = idx4[tap * 128 + m];
                const float* xp = xb + ((size_t)c << 12);
                float s = cf.x * __ldg(xp + ix.x) + cf.y * __ldg(xp + ix.y)
                        + cf.z * __ldg(xp + ix.z) + cf.w * __ldg(xp + ix.w);
                __nv_bfloat16 hi = __float2bfloat16(s);
                float hf = __bfloat162float(hi);
                __nv_bfloat16 lo = __float2bfloat16(s - hf);
                hb[jj] = *(unsigned short*)&hi;
                lb[jj] = *(unsigned short*)&lo;
            }
            int off = m * 144 + (kb0 + gseg * 8) * 2;
            *(uint4*)(smem + SM_A_HI + off) = *(uint4*)hb;
            *(uint4*)(smem + SM_A_LO + off) = *(uint4*)lb;
        }
        __syncthreads();

        // ---- warp GEMM over this K64 chunk
#pragma unroll
        for (int s = 0; s < 4; s++) {
            uint32_t ah[2][4], al[2][4];
#pragma unroll
            for (int f = 0; f < 2; f++) {
                int r0 = wm + f * 16 + g;
                int w0 = r0 * APITCH_W + 8 * s + t;
                int w1 = (r0 + 8) * APITCH_W + 8 * s + t;
                ah[f][0] = AsH[w0]; ah[f][1] = AsH[w1];
                ah[f][2] = AsH[w0 + 4]; ah[f][3] = AsH[w1 + 4];
                al[f][0] = AsL[w0]; al[f][1] = AsL[w1];
                al[f][2] = AsL[w0 + 4]; al[f][3] = AsL[w1 + 4];
            }
#pragma unroll
            for (int ni = 0; ni < 8; ni++) {
                int n = wn + ni * 8 + g;
                int wB = n * APITCH_W + 8 * s + t;
                uint32_t bh[2], bl[2];
                bh[0] = BsH[wB]; bh[1] = BsH[wB + 4];
                bl[0] = BsL[wB]; bl[1] = BsL[wB + 4];
#pragma unroll
                for (int f = 0; f < 2; f++) {
                    mma16816(acc[f][ni], ah[f], bh);
                    mma16816(acc[f][ni], ah[f], bl);
                    mma16816(acc[f][ni], al[f], bh);
                }
            }
        }
    }

    // ---- epilogue: D mapping d0=D[g][2t], d1=D[g][2t+1], d2=D[g+8][2t], d3=D[g+8][2t+1]
#pragma unroll
    for (int f = 0; f < 2; f++) {
        int m0 = wm + f * 16 + g;
        int m1 = m0 + 8;
        int p0 = (h0 + (m0 >> 6)) * 64 + (m0 & 63);
        int p1 = (h0 + (m1 >> 6)) * 64 + (m1 & 63);
#pragma unroll
        for (int ni = 0; ni < 8; ni++) {
            int oc = wn + ni * 8 + 2 * t;
            float b0 = __ldg(bias + oc), b1 = __ldg(bias + oc + 1);
            float* y0 = g_y + ((size_t)(b * 256 + oc) << 12);
            float* y1 = g_y + ((size_t)(b * 256 + oc + 1) << 12);
            y0[p0] = acc[f][ni][0] + b0;
            y1[p0] = acc[f][ni][1] + b1;
            y0[p1] = acc[f][ni][2] + b0;
            y1[p1] = acc[f][ni][3] + b1;
        }
    }
}

// ============ Kernel 3: per-channel mean/var -> scale/shift ============
__global__ void __launch_bounds__(256) stats_kernel(const float* __restrict__ gamma,
                                                    const float* __restrict__ beta) {
    __shared__ float ss[256], sq[256];
    const int ch = blockIdx.x, tid = threadIdx.x;
    float s = 0.f, q = 0.f;
    for (int b = 0; b < 8; b++) {
        const float4* y4 = (const float4*)(g_y + ((size_t)(b * 256 + ch) << 12));
#pragma unroll
        for (int r = 0; r < 4; r++) {
            float4 v = y4[r * 256 + tid];
            s += (v.x + v.y) + (v.z + v.w);
            q += v.x * v.x + v.y * v.y + v.z * v.z + v.w * v.w;
        }
    }
    ss[tid] = s; sq[tid] = q;
    __syncthreads();
    for (int o = 128; o > 0; o >>= 1) {
        if (tid < o) { ss[tid] += ss[tid + o]; sq[tid] += sq[tid + o]; }
        __syncthreads();
    }
    if (tid == 0) {
        float mean = ss[0] * (1.f / 32768.f);
        float var  = sq[0] * (1.f / 32768.f) - mean * mean;
        float a = __ldg(gamma + ch) * rsqrtf(var + 1e-5f);
        g_a[ch] = a;
        g_bsh[ch] = __ldg(beta + ch) - mean * a;
    }
}

// ============ Kernel 4: normalize + ReLU ============
__global__ void __launch_bounds__(256) norm_kernel(float* __restrict__ out) {
    int i4 = blockIdx.x * 256 + threadIdx.x;
    int ch = (i4 >> 10) & 255;
    float a = g_a[ch], sh = g_bsh[ch];
    float4 v = ((const float4*)g_y)[i4];
    v.x = fmaxf(v.x * a + sh, 0.f);
    v.y = fmaxf(v.y * a + sh, 0.f);
    v.z = fmaxf(v.z * a + sh, 0.f);
    v.w = fmaxf(v.w * a + sh, 0.f);
    ((float4*)out)[i4] = v;
}

extern "C" void kernel_launch(void* const* d_in, const int* in_sizes, int n_in,
                              void* d_out, int out_size) {
    const float* x      = (const float*)d_in[0];
    const float* w_off  = (const float*)d_in[1];
    const float* b_off  = (const float*)d_in[2];
    const float* weight = (const float*)d_in[3];
    const float* bias   = (const float*)d_in[4];
    const float* gamma  = (const float*)d_in[5];
    const float* beta   = (const float*)d_in[6];
    float* out = (float*)d_out;

    static bool attr_set = false;
    if (!attr_set) {
        cudaFuncSetAttribute(deform_gemm_tc, cudaFuncAttributeMaxDynamicSharedMemorySize, SMEM_TC);
        attr_set = true;
    }

    offset_conv<<<256, 128>>>(x, w_off, b_off);
    convert_w<<<1152, 512>>>(weight);
    deform_gemm_tc<<<256, 512, SMEM_TC>>>(x, bias);
    stats_kernel<<<256, 256>>>(gamma, beta);
    norm_kernel<<<8192, 256>>>(out);
}

// round 13
// speedup vs baseline: 2.6805x; 1.1626x over previous
#include <cuda_runtime.h>
#include <cuda_fp16.h>
#include <cuda_bf16.h>
#include <cstdint>

typedef unsigned long long ull;
#define PLANE 4096
#define KTOT  2304

__device__ float g_om[8 * 27 * PLANE];
__device__ float g_y [8 * 256 * PLANE];
__device__ float g_a [256];
__device__ float g_bsh[256];
__device__ __half g_wh[256 * KTOT];

__device__ __forceinline__ ull fma2(ull a, ull b, ull c) {
    ull d; asm("fma.rn.f32x2 %0, %1, %2, %3;" : "=l"(d) : "l"(a), "l"(b), "l"(c)); return d;
}
__device__ __forceinline__ ull pack2(float lo, float hi) {
    ull v; asm("mov.b64 %0, {%1, %2};" : "=l"(v) : "f"(lo), "f"(hi)); return v;
}
__device__ __forceinline__ float2 unpack2(ull v) {
    float2 f; asm("mov.b64 {%0, %1}, %2;" : "=f"(f.x), "=f"(f.y) : "l"(v)); return f;
}
__device__ __forceinline__ void mma16816(float* d, const uint32_t* a, const uint32_t* b) {
    asm volatile(
        "mma.sync.aligned.m16n8k16.row.col.f32.f16.f16.f32 "
        "{%0,%1,%2,%3}, {%4,%5,%6,%7}, {%8,%9}, {%0,%1,%2,%3};"
        : "+f"(d[0]), "+f"(d[1]), "+f"(d[2]), "+f"(d[3])
        : "r"(a[0]), "r"(a[1]), "r"(a[2]), "r"(a[3]), "r"(b[0]), "r"(b[1]));
}
__device__ __forceinline__ uint32_t smem_u32(const void* p) {
    uint32_t a;
    asm("{ .reg .u64 t; cvta.to.shared.u64 t, %1; cvt.u32.u64 %0, t; }" : "=r"(a) : "l"(p));
    return a;
}
__device__ __forceinline__ void cp16(uint32_t dst, const void* src) {
    asm volatile("cp.async.ca.shared.global [%0], [%1], 16;" :: "r"(dst), "l"(src));
}
#define CP_COMMIT() asm volatile("cp.async.commit_group;" ::: "memory")
#define CP_WAIT0()  asm volatile("cp.async.wait_group 0;" ::: "memory")

// ============ Kernel 1: offset conv (27ch 3x3) ============
__global__ void __launch_bounds__(128) offset_conv(const float* __restrict__ x,
                                                   const float* __restrict__ woff,
                                                   const float* __restrict__ boff) {
    __shared__ float sw[27 * 32 * 12];
    const int tid = threadIdx.x;
    const int b = blockIdx.x >> 5;
    const int h = ((blockIdx.x & 31) << 1) + (tid >> 6);
    const int w = tid & 63;

    ull acc2[27]; float acc1[27];
#pragma unroll
    for (int oc = 0; oc < 27; oc++) { acc2[oc] = 0ULL; acc1[oc] = 0.f; }

    for (int c0 = 0; c0 < 256; c0 += 32) {
        __syncthreads();
        for (int i = tid; i < 27 * 32 * 9; i += 128) {
            int oc = i / 288, rem = i - oc * 288;
            int cl = rem / 9, j = rem - cl * 9;
            sw[(oc * 32 + cl) * 12 + j] = __ldg(&woff[(oc * 256 + c0 + cl) * 9 + j]);
        }
        __syncthreads();
        for (int cl = 0; cl < 32; cl++) {
            const float* xc = x + ((size_t)(b * 256 + c0 + cl) << 12);
            float v[9];
#pragma unroll
            for (int a = 0; a < 3; a++)
#pragma unroll
                for (int e = 0; e < 3; e++) {
                    int hh = h + a - 1, ww = w + e - 1;
                    bool ok = (hh >= 0) & (hh < 64) & (ww >= 0) & (ww < 64);
                    v[a * 3 + e] = ok ? __ldg(xc + hh * 64 + ww) : 0.f;
                }
            ull p0 = pack2(v[0], v[1]), p1 = pack2(v[2], v[3]);
            ull p2 = pack2(v[4], v[5]), p3 = pack2(v[6], v[7]);
            float v8 = v[8];
            const float* wb = sw + cl * 12;
#pragma unroll
            for (int oc = 0; oc < 27; oc++) {
                const float* wr = wb + oc * 384;
                ulonglong2 w01 = *(const ulonglong2*)(wr);
                ulonglong2 w23 = *(const ulonglong2*)(wr + 4);
                acc2[oc] = fma2(p0, w01.x, acc2[oc]);
                acc2[oc] = fma2(p1, w01.y, acc2[oc]);
                acc2[oc] = fma2(p2, w23.x, acc2[oc]);
                acc2[oc] = fma2(p3, w23.y, acc2[oc]);
                acc1[oc] = fmaf(v8, wr[8], acc1[oc]);
            }
        }
    }
#pragma unroll
    for (int oc = 0; oc < 27; oc++) {
        float2 f = unpack2(acc2[oc]);
        g_om[((size_t)(b * 27 + oc) << 12) + h * 64 + w] = f.x + f.y + acc1[oc] + __ldg(boff + oc);
    }
}

// ============ Kernel 1b: weight -> fp16 ============
__global__ void __launch_bounds__(512) convert_w(const float* __restrict__ weight) {
    int i = blockIdx.x * 512 + threadIdx.x;      // 589824 total
    g_wh[i] = __float2half_rn(__ldg(weight + i));
}

// ============ Kernel 2: deformable gather + split-fp16 mma.sync GEMM ============
// CTA per (b, h-pair): M=128 px, N=256 oc, K=2304 in 36 chunks of 64.
// Double-buffered A(hi/lo) + B; one __syncthreads per chunk; B via cp.async.
// Pitch 144 B (36 words) -> conflict-free LDS.32 operand fetch.
#define APITCH_W 36
#define A_BYTES  18432                  // 128 * 144
#define B_BYTES  36864                  // 256 * 144
#define SM_AH    0                      // 2 x 18432
#define SM_AL    36864                  // 2 x 18432
#define SM_B     73728                  // 2 x 36864
#define SM_COEF  147456                 // 1152 * 16
#define SM_IDX   165888                 // 1152 * 8
#define SMEM_TC  175104

__global__ void __launch_bounds__(512, 1) deform_gemm_tc(const float* __restrict__ x,
                                                         const float* __restrict__ bias) {
    extern __shared__ char smem[];
    const uint32_t smb = smem_u32(smem);
    const int tid = threadIdx.x;
    const int wid = tid >> 5;
    const int lane = tid & 31;
    const int b = blockIdx.x >> 5;
    const int h0 = (blockIdx.x & 31) << 1;

    float4*  coef4 = (float4*)(smem + SM_COEF);
    ushort4* idx4  = (ushort4*)(smem + SM_IDX);

    // ---- prologue: bilinear coefs per (tap, m)
    for (int i = tid; i < 1152; i += 512) {
        int tap = i >> 7, m = i & 127;
        int r = m >> 6, px = m & 63;
        int h = h0 + r;
        const float* omb = g_om + ((size_t)(b * 27) << 12) + h * 64 + px;
        float offh = omb[(size_t)(2 * tap) << 12];
        float offw = omb[(size_t)(2 * tap + 1) << 12];
        float mv   = omb[(size_t)(18 + tap) << 12];
        float mask = 1.f / (1.f + __expf(-mv));
        int kh = tap / 3, kw = tap - kh * 3;
        float ph = (float)(h + kh - 1) + offh;
        float pw = (float)(px + kw - 1) + offw;
        float fh0 = floorf(ph), fw0 = floorf(pw);
        int hh0 = (int)fh0, ww0 = (int)fw0;
        float lh = ph - fh0, lw = pw - fw0;
        float hh = 1.f - lh, hw = 1.f - lw;
        bool vh0 = (hh0 >= 0) & (hh0 < 64), vh1 = (hh0 >= -1) & (hh0 < 63);
        bool vw0 = (ww0 >= 0) & (ww0 < 64), vw1 = (ww0 >= -1) & (ww0 < 63);
        int ch0 = min(max(hh0, 0), 63), ch1 = min(max(hh0 + 1, 0), 63);
        int cw0 = min(max(ww0, 0), 63), cw1 = min(max(ww0 + 1, 0), 63);
        float4 cf;
        cf.x = (vh0 & vw0) ? hh * hw * mask : 0.f;
        cf.y = (vh0 & vw1) ? hh * lw * mask : 0.f;
        cf.z = (vh1 & vw0) ? lh * hw * mask : 0.f;
        cf.w = (vh1 & vw1) ? lh * lw * mask : 0.f;
        coef4[i] = cf;
        ushort4 ix;
        ix.x = (unsigned short)(ch0 * 64 + cw0);
        ix.y = (unsigned short)(ch0 * 64 + cw1);
        ix.z = (unsigned short)(ch1 * 64 + cw0);
        ix.w = (unsigned short)(ch1 * 64 + cw1);
        idx4[i] = ix;
    }
    // CRITICAL: tables are read cross-thread by GATHER_A below.
    __syncthreads();

    const float* xb = x + ((size_t)(b * 256) << 12);
    const int m   = tid & 127;          // gather: M row owned
    const int kb0 = (tid >> 7) << 4;    // gather: k sub-range

    const int g = lane >> 2, t = lane & 3;
    const int wm = (wid & 3) << 5;      // warp M origin
    const int wn = (wid >> 2) << 6;     // warp N origin

    float acc[2][8][4];
#pragma unroll
    for (int f = 0; f < 2; f++)
#pragma unroll
        for (int ni = 0; ni < 8; ni++)
#pragma unroll
            for (int e = 0; e < 4; e++) acc[f][ni][e] = 0.f;

#define STAGE_B(CC, BUF) do { \
        uint32_t bdst = smb + SM_B + (BUF) * B_BYTES; \
        _Pragma("unroll") \
        for (int i = 0; i < 4; i++) { \
            int lin = i * 512 + tid; \
            int oc = lin >> 3, j = lin & 7; \
            cp16(bdst + oc * 144 + j * 16, g_wh + (size_t)oc * KTOT + (CC) * 64 + j * 8); \
        } \
        CP_COMMIT(); \
    } while (0)

#define GATHER_A(CC, BUF) do { \
        char* ah_ = smem + SM_AH + (BUF) * A_BYTES; \
        char* al_ = smem + SM_AL + (BUF) * A_BYTES; \
        _Pragma("unroll") \
        for (int gseg = 0; gseg < 2; gseg++) { \
            unsigned short hb[8], lb[8]; \
            _Pragma("unroll") \
            for (int jj = 0; jj < 8; jj++) { \
                int kl = kb0 + gseg * 8 + jj; \
                int kg = (CC) * 64 + kl; \
                int c  = kg / 9; \
                int tap = kg - c * 9; \
                float4  cf = coef4[tap * 128 + m]; \
                ushort4 ix = idx4[tap * 128 + m]; \
                const float* xp = xb + ((size_t)c << 12); \
                float s = cf.x * __ldg(xp + ix.x) + cf.y * __ldg(xp + ix.y) \
                        + cf.z * __ldg(xp + ix.z) + cf.w * __ldg(xp + ix.w); \
                __half hi = __float2half_rn(s); \
                __half lo = __float2half_rn(s - __half2float(hi)); \
                hb[jj] = *(unsigned short*)&hi; \
                lb[jj] = *(unsigned short*)&lo; \
            } \
            int off = m * 144 + (kb0 + gseg * 8) * 2; \
            *(uint4*)(ah_ + off) = *(uint4*)hb; \
            *(uint4*)(al_ + off) = *(uint4*)lb; \
        } \
    } while (0)

    // prologue: stage chunk 0 into buffer 0
    STAGE_B(0, 0);
    GATHER_A(0, 0);
    CP_WAIT0();
    __syncthreads();

    for (int cc = 0; cc < 36; cc++) {
        const int buf = cc & 1;
        if (cc + 1 < 36) STAGE_B(cc + 1, buf ^ 1);

        const uint32_t* AsH = (const uint32_t*)(smem + SM_AH + buf * A_BYTES);
        const uint32_t* AsL = (const uint32_t*)(smem + SM_AL + buf * A_BYTES);
        const uint32_t* Bs  = (const uint32_t*)(smem + SM_B  + buf * B_BYTES);

#pragma unroll
        for (int s = 0; s < 4; s++) {
            uint32_t ah[2][4], al[2][4];
#pragma unroll
            for (int f = 0; f < 2; f++) {
                int r0 = wm + f * 16 + g;
                int w0 = r0 * APITCH_W + 8 * s + t;
                int w1 = (r0 + 8) * APITCH_W + 8 * s + t;
                ah[f][0] = AsH[w0]; ah[f][1] = AsH[w1];
                ah[f][2] = AsH[w0 + 4]; ah[f][3] = AsH[w1 + 4];
                al[f][0] = AsL[w0]; al[f][1] = AsL[w1];
                al[f][2] = AsL[w0 + 4]; al[f][3] = AsL[w1 + 4];
            }
#pragma unroll
            for (int ni = 0; ni < 8; ni++) {
                int n = wn + ni * 8 + g;
                int wB = n * APITCH_W + 8 * s + t;
                uint32_t bh[2];
                bh[0] = Bs[wB]; bh[1] = Bs[wB + 4];
#pragma unroll
                for (int f = 0; f < 2; f++) {
                    mma16816(acc[f][ni], ah[f], bh);
                    mma16816(acc[f][ni], al[f], bh);
                }
            }
        }

        if (cc + 1 < 36) GATHER_A(cc + 1, buf ^ 1);
        CP_WAIT0();
        __syncthreads();
    }

    // ---- epilogue: d0=D[g][2t], d1=D[g][2t+1], d2=D[g+8][2t], d3=D[g+8][2t+1]
#pragma unroll
    for (int f = 0; f < 2; f++) {
        int m0 = wm + f * 16 + g;
        int m1 = m0 + 8;
        int p0 = (h0 + (m0 >> 6)) * 64 + (m0 & 63);
        int p1 = (h0 + (m1 >> 6)) * 64 + (m1 & 63);
#pragma unroll
        for (int ni = 0; ni < 8; ni++) {
            int oc = wn + ni * 8 + 2 * t;
            float b0 = __ldg(bias + oc), b1 = __ldg(bias + oc + 1);
            float* y0 = g_y + ((size_t)(b * 256 + oc) << 12);
            float* y1 = g_y + ((size_t)(b * 256 + oc + 1) << 12);
            y0[p0] = acc[f][ni][0] + b0;
            y1[p0] = acc[f][ni][1] + b1;
            y0[p1] = acc[f][ni][2] + b0;
            y1[p1] = acc[f][ni][3] + b1;
        }
    }
}

// ============ Kernel 3: per-channel mean/var -> scale/shift ============
__global__ void __launch_bounds__(256) stats_kernel(const float* __restrict__ gamma,
                                                    const float* __restrict__ beta) {
    __shared__ float ss[256], sq[256];
    const int ch = blockIdx.x, tid = threadIdx.x;
    float s = 0.f, q = 0.f;
    for (int b = 0; b < 8; b++) {
        const float4* y4 = (const float4*)(g_y + ((size_t)(b * 256 + ch) << 12));
#pragma unroll
        for (int r = 0; r < 4; r++) {
            float4 v = y4[r * 256 + tid];
            s += (v.x + v.y) + (v.z + v.w);
            q += v.x * v.x + v.y * v.y + v.z * v.z + v.w * v.w;
        }
    }
    ss[tid] = s; sq[tid] = q;
    __syncthreads();
    for (int o = 128; o > 0; o >>= 1) {
        if (tid < o) { ss[tid] += ss[tid + o]; sq[tid] += sq[tid + o]; }
        __syncthreads();
    }
    if (tid == 0) {
        float mean = ss[0] * (1.f / 32768.f);
        float var  = sq[0] * (1.f / 32768.f) - mean * mean;
        float a = __ldg(gamma + ch) * rsqrtf(var + 1e-5f);
        g_a[ch] = a;
        g_bsh[ch] = __ldg(beta + ch) - mean * a;
    }
}

// ============ Kernel 4: normalize + ReLU ============
__global__ void __launch_bounds__(256) norm_kernel(float* __restrict__ out) {
    int i4 = blockIdx.x * 256 + threadIdx.x;
    int ch = (i4 >> 10) & 255;
    float a = g_a[ch], sh = g_bsh[ch];
    float4 v = ((const float4*)g_y)[i4];
    v.x = fmaxf(v.x * a + sh, 0.f);
    v.y = fmaxf(v.y * a + sh, 0.f);
    v.z = fmaxf(v.z * a + sh, 0.f);
    v.w = fmaxf(v.w * a + sh, 0.f);
    ((float4*)out)[i4] = v;
}

extern "C" void kernel_launch(void* const* d_in, const int* in_sizes, int n_in,
                              void* d_out, int out_size) {
    const float* x      = (const float*)d_in[0];
    const float* w_off  = (const float*)d_in[1];
    const float* b_off  = (const float*)d_in[2];
    const float* weight = (const float*)d_in[3];
    const float* bias   = (const float*)d_in[4];
    const float* gamma  = (const float*)d_in[5];
    const float* beta   = (const float*)d_in[6];
    float* out = (float*)d_out;

    static bool attr_set = false;
    if (!attr_set) {
        cudaFuncSetAttribute(deform_gemm_tc, cudaFuncAttributeMaxDynamicSharedMemorySize, SMEM_TC);
        attr_set = true;
    }

    offset_conv<<<256, 128>>>(x, w_off, b_off);
    convert_w<<<1152, 512>>>(weight);
    deform_gemm_tc<<<256, 512, SMEM_TC>>>(x, bias);
    stats_kernel<<<256, 256>>>(gamma, beta);
    norm_kernel<<<8192, 256>>>(out);
}

// round 14
// speedup vs baseline: 3.0147x; 1.1247x over previous
#include <cuda_runtime.h>
#include <cuda_fp16.h>
#include <cuda_bf16.h>
#include <cstdint>

typedef unsigned long long ull;
#define PLANE 4096
#define KTOT  2304

__device__ float g_om[2 * 8 * 27 * PLANE];   // [half][b][27][h][w] partial sums
__device__ float g_y [8 * 256 * PLANE];
__device__ float g_a [256];
__device__ float g_bsh[256];
__device__ __half g_wh[256 * KTOT];

__device__ __forceinline__ ull fma2(ull a, ull b, ull c) {
    ull d; asm("fma.rn.f32x2 %0, %1, %2, %3;" : "=l"(d) : "l"(a), "l"(b), "l"(c)); return d;
}
__device__ __forceinline__ ull pack2(float lo, float hi) {
    ull v; asm("mov.b64 %0, {%1, %2};" : "=l"(v) : "f"(lo), "f"(hi)); return v;
}
__device__ __forceinline__ float2 unpack2(ull v) {
    float2 f; asm("mov.b64 {%0, %1}, %2;" : "=f"(f.x), "=f"(f.y) : "l"(v)); return f;
}
__device__ __forceinline__ void mma16816(float* d, const uint32_t* a, const uint32_t* b) {
    asm volatile(
        "mma.sync.aligned.m16n8k16.row.col.f32.f16.f16.f32 "
        "{%0,%1,%2,%3}, {%4,%5,%6,%7}, {%8,%9}, {%0,%1,%2,%3};"
        : "+f"(d[0]), "+f"(d[1]), "+f"(d[2]), "+f"(d[3])
        : "r"(a[0]), "r"(a[1]), "r"(a[2]), "r"(a[3]), "r"(b[0]), "r"(b[1]));
}
__device__ __forceinline__ uint32_t smem_u32(const void* p) {
    uint32_t a;
    asm("{ .reg .u64 t; cvta.to.shared.u64 t, %1; cvt.u32.u64 %0, t; }" : "=r"(a) : "l"(p));
    return a;
}
__device__ __forceinline__ void cp16(uint32_t dst, const void* src) {
    asm volatile("cp.async.ca.shared.global [%0], [%1], 16;" :: "r"(dst), "l"(src));
}
#define CP_COMMIT() asm volatile("cp.async.commit_group;" ::: "memory")
#define CP_WAIT0()  asm volatile("cp.async.wait_group 0;" ::: "memory")

// ============ Kernel 1: offset conv (27ch 3x3), channel-split x2 ============
// 512 blocks: half = blk>>8 handles 128 input channels, writes partial plane.
__global__ void __launch_bounds__(128) offset_conv(const float* __restrict__ x,
                                                   const float* __restrict__ woff,
                                                   const float* __restrict__ boff) {
    __shared__ float sw[27 * 32 * 12];
    const int tid = threadIdx.x;
    const int half = blockIdx.x >> 8;
    const int rest = blockIdx.x & 255;
    const int b = rest >> 5;
    const int h = ((rest & 31) << 1) + (tid >> 6);
    const int w = tid & 63;
    const int cbase = half << 7;

    ull acc2[27]; float acc1[27];
#pragma unroll
    for (int oc = 0; oc < 27; oc++) { acc2[oc] = 0ULL; acc1[oc] = 0.f; }

    for (int c0 = cbase; c0 < cbase + 128; c0 += 32) {
        __syncthreads();
        for (int i = tid; i < 27 * 32 * 9; i += 128) {
            int oc = i / 288, rem = i - oc * 288;
            int cl = rem / 9, j = rem - cl * 9;
            sw[(oc * 32 + cl) * 12 + j] = __ldg(&woff[(oc * 256 + c0 + cl) * 9 + j]);
        }
        __syncthreads();
        for (int cl = 0; cl < 32; cl++) {
            const float* xc = x + ((size_t)(b * 256 + c0 + cl) << 12);
            float v[9];
#pragma unroll
            for (int a = 0; a < 3; a++)
#pragma unroll
                for (int e = 0; e < 3; e++) {
                    int hh = h + a - 1, ww = w + e - 1;
                    bool ok = (hh >= 0) & (hh < 64) & (ww >= 0) & (ww < 64);
                    v[a * 3 + e] = ok ? __ldg(xc + hh * 64 + ww) : 0.f;
                }
            ull p0 = pack2(v[0], v[1]), p1 = pack2(v[2], v[3]);
            ull p2 = pack2(v[4], v[5]), p3 = pack2(v[6], v[7]);
            float v8 = v[8];
            const float* wb = sw + cl * 12;
#pragma unroll
            for (int oc = 0; oc < 27; oc++) {
                const float* wr = wb + oc * 384;
                ulonglong2 w01 = *(const ulonglong2*)(wr);
                ulonglong2 w23 = *(const ulonglong2*)(wr + 4);
                acc2[oc] = fma2(p0, w01.x, acc2[oc]);
                acc2[oc] = fma2(p1, w01.y, acc2[oc]);
                acc2[oc] = fma2(p2, w23.x, acc2[oc]);
                acc2[oc] = fma2(p3, w23.y, acc2[oc]);
                acc1[oc] = fmaf(v8, wr[8], acc1[oc]);
            }
        }
    }
    float* omh = g_om + (size_t)half * (8 * 27 * PLANE);
#pragma unroll
    for (int oc = 0; oc < 27; oc++) {
        float2 f = unpack2(acc2[oc]);
        float r = f.x + f.y + acc1[oc];
        if (half == 0) r += __ldg(boff + oc);   // bias folded into half 0
        omh[((size_t)(b * 27 + oc) << 12) + h * 64 + w] = r;
    }
}

// ============ Kernel 1b: weight -> fp16 ============
__global__ void __launch_bounds__(512) convert_w(const float* __restrict__ weight) {
    int i = blockIdx.x * 512 + threadIdx.x;      // 589824 total
    g_wh[i] = __float2half_rn(__ldg(weight + i));
}

// ============ Kernel 2: deformable gather + fp16 mma.sync GEMM ============
// CTA per (b, h-pair): M=128 px, N=256 oc, K=2304 in 36 chunks of 64.
// Single fp16 A (B fp16 too); double-buffered; one sync/chunk; B via cp.async.
// Pitch 144 B (36 words) -> conflict-free LDS.32 operand fetch.
#define APITCH_W 36
#define A_BYTES  18432                  // 128 * 144
#define B_BYTES  36864                  // 256 * 144
#define SM_AH    0                      // 2 x 18432
#define SM_B     36864                  // 2 x 36864
#define SM_COEF  110592                 // 1152 * 16
#define SM_IDX   129024                 // 1152 * 8
#define SMEM_TC  138240

__global__ void __launch_bounds__(512, 1) deform_gemm_tc(const float* __restrict__ x,
                                                         const float* __restrict__ bias) {
    extern __shared__ char smem[];
    const uint32_t smb = smem_u32(smem);
    const int tid = threadIdx.x;
    const int wid = tid >> 5;
    const int lane = tid & 31;
    const int b = blockIdx.x >> 5;
    const int h0 = (blockIdx.x & 31) << 1;

    float4*  coef4 = (float4*)(smem + SM_COEF);
    ushort4* idx4  = (ushort4*)(smem + SM_IDX);

    // ---- prologue: bilinear coefs per (tap, m); sums the two offset-conv halves
    for (int i = tid; i < 1152; i += 512) {
        int tap = i >> 7, m = i & 127;
        int r = m >> 6, px = m & 63;
        int h = h0 + r;
        const float* omb  = g_om + ((size_t)(b * 27) << 12) + h * 64 + px;
        const float* omb2 = omb + (size_t)(8 * 27 * PLANE);
        float offh = omb[(size_t)(2 * tap) << 12]     + omb2[(size_t)(2 * tap) << 12];
        float offw = omb[(size_t)(2 * tap + 1) << 12] + omb2[(size_t)(2 * tap + 1) << 12];
        float mv   = omb[(size_t)(18 + tap) << 12]    + omb2[(size_t)(18 + tap) << 12];
        float mask = 1.f / (1.f + __expf(-mv));
        int kh = tap / 3, kw = tap - kh * 3;
        float ph = (float)(h + kh - 1) + offh;
        float pw = (float)(px + kw - 1) + offw;
        float fh0 = floorf(ph), fw0 = floorf(pw);
        int hh0 = (int)fh0, ww0 = (int)fw0;
        float lh = ph - fh0, lw = pw - fw0;
        float hh = 1.f - lh, hw = 1.f - lw;
        bool vh0 = (hh0 >= 0) & (hh0 < 64), vh1 = (hh0 >= -1) & (hh0 < 63);
        bool vw0 = (ww0 >= 0) & (ww0 < 64), vw1 = (ww0 >= -1) & (ww0 < 63);
        int ch0 = min(max(hh0, 0), 63), ch1 = min(max(hh0 + 1, 0), 63);
        int cw0 = min(max(ww0, 0), 63), cw1 = min(max(ww0 + 1, 0), 63);
        float4 cf;
        cf.x = (vh0 & vw0) ? hh * hw * mask : 0.f;
        cf.y = (vh0 & vw1) ? hh * lw * mask : 0.f;
        cf.z = (vh1 & vw0) ? lh * hw * mask : 0.f;
        cf.w = (vh1 & vw1) ? lh * lw * mask : 0.f;
        coef4[i] = cf;
        ushort4 ix;
        ix.x = (unsigned short)(ch0 * 64 + cw0);
        ix.y = (unsigned short)(ch0 * 64 + cw1);
        ix.z = (unsigned short)(ch1 * 64 + cw0);
        ix.w = (unsigned short)(ch1 * 64 + cw1);
        idx4[i] = ix;
    }
    // tables are read cross-thread by GATHER_A below
    __syncthreads();

    const float* xb = x + ((size_t)(b * 256) << 12);
    const int m   = tid & 127;          // gather: M row owned
    const int kb0 = (tid >> 7) << 4;    // gather: k sub-range

    const int g = lane >> 2, t = lane & 3;
    const int wm = (wid & 3) << 5;      // warp M origin
    const int wn = (wid >> 2) << 6;     // warp N origin

    float acc[2][8][4];
#pragma unroll
    for (int f = 0; f < 2; f++)
#pragma unroll
        for (int ni = 0; ni < 8; ni++)
#pragma unroll
            for (int e = 0; e < 4; e++) acc[f][ni][e] = 0.f;

#define STAGE_B(CC, BUF) do { \
        uint32_t bdst = smb + SM_B + (BUF) * B_BYTES; \
        _Pragma("unroll") \
        for (int i = 0; i < 4; i++) { \
            int lin = i * 512 + tid; \
            int oc = lin >> 3, j = lin & 7; \
            cp16(bdst + oc * 144 + j * 16, g_wh + (size_t)oc * KTOT + (CC) * 64 + j * 8); \
        } \
        CP_COMMIT(); \
    } while (0)

#define GATHER_A(CC, BUF) do { \
        char* ah_ = smem + SM_AH + (BUF) * A_BYTES; \
        _Pragma("unroll") \
        for (int gseg = 0; gseg < 2; gseg++) { \
            unsigned short hb[8]; \
            _Pragma("unroll") \
            for (int jj = 0; jj < 8; jj++) { \
                int kl = kb0 + gseg * 8 + jj; \
                int kg = (CC) * 64 + kl; \
                int c  = kg / 9; \
                int tap = kg - c * 9; \
                float4  cf = coef4[tap * 128 + m]; \
                ushort4 ix = idx4[tap * 128 + m]; \
                const float* xp = xb + ((size_t)c << 12); \
                float s = cf.x * __ldg(xp + ix.x) + cf.y * __ldg(xp + ix.y) \
                        + cf.z * __ldg(xp + ix.z) + cf.w * __ldg(xp + ix.w); \
                __half hi = __float2half_rn(s); \
                hb[jj] = *(unsigned short*)&hi; \
            } \
            int off = m * 144 + (kb0 + gseg * 8) * 2; \
            *(uint4*)(ah_ + off) = *(uint4*)hb; \
        } \
    } while (0)

    // prologue: stage chunk 0 into buffer 0
    STAGE_B(0, 0);
    GATHER_A(0, 0);
    CP_WAIT0();
    __syncthreads();

    for (int cc = 0; cc < 36; cc++) {
        const int buf = cc & 1;
        if (cc + 1 < 36) STAGE_B(cc + 1, buf ^ 1);

        const uint32_t* AsH = (const uint32_t*)(smem + SM_AH + buf * A_BYTES);
        const uint32_t* Bs  = (const uint32_t*)(smem + SM_B  + buf * B_BYTES);

#pragma unroll
        for (int s = 0; s < 4; s++) {
            uint32_t ah[2][4];
#pragma unroll
            for (int f = 0; f < 2; f++) {
                int r0 = wm + f * 16 + g;
                int w0 = r0 * APITCH_W + 8 * s + t;
                int w1 = (r0 + 8) * APITCH_W + 8 * s + t;
                ah[f][0] = AsH[w0]; ah[f][1] = AsH[w1];
                ah[f][2] = AsH[w0 + 4]; ah[f][3] = AsH[w1 + 4];
            }
#pragma unroll
            for (int ni = 0; ni < 8; ni++) {
                int n = wn + ni * 8 + g;
                int wB = n * APITCH_W + 8 * s + t;
                uint32_t bh[2];
                bh[0] = Bs[wB]; bh[1] = Bs[wB + 4];
#pragma unroll
                for (int f = 0; f < 2; f++)
                    mma16816(acc[f][ni], ah[f], bh);
            }
        }

        if (cc + 1 < 36) GATHER_A(cc + 1, buf ^ 1);
        CP_WAIT0();
        __syncthreads();
    }

    // ---- epilogue: d0=D[g][2t], d1=D[g][2t+1], d2=D[g+8][2t], d3=D[g+8][2t+1]
#pragma unroll
    for (int f = 0; f < 2; f++) {
        int m0 = wm + f * 16 + g;
        int m1 = m0 + 8;
        int p0 = (h0 + (m0 >> 6)) * 64 + (m0 & 63);
        int p1 = (h0 + (m1 >> 6)) * 64 + (m1 & 63);
#pragma unroll
        for (int ni = 0; ni < 8; ni++) {
            int oc = wn + ni * 8 + 2 * t;
            float b0 = __ldg(bias + oc), b1 = __ldg(bias + oc + 1);
            float* y0 = g_y + ((size_t)(b * 256 + oc) << 12);
            float* y1 = g_y + ((size_t)(b * 256 + oc + 1) << 12);
            y0[p0] = acc[f][ni][0] + b0;
            y1[p0] = acc[f][ni][1] + b1;
            y0[p1] = acc[f][ni][2] + b0;
            y1[p1] = acc[f][ni][3] + b1;
        }
    }
}

// ============ Kernel 3: per-channel mean/var -> scale/shift ============
__global__ void __launch_bounds__(256) stats_kernel(const float* __restrict__ gamma,
                                                    const float* __restrict__ beta) {
    __shared__ float ss[256], sq[256];
    const int ch = blockIdx.x, tid = threadIdx.x;
    float s = 0.f, q = 0.f;
    for (int b = 0; b < 8; b++) {
        const float4* y4 = (const float4*)(g_y + ((size_t)(b * 256 + ch) << 12));
#pragma unroll
        for (int r = 0; r < 4; r++) {
            float4 v = y4[r * 256 + tid];
            s += (v.x + v.y) + (v.z + v.w);
            q += v.x * v.x + v.y * v.y + v.z * v.z + v.w * v.w;
        }
    }
    ss[tid] = s; sq[tid] = q;
    __syncthreads();
    for (int o = 128; o > 0; o >>= 1) {
        if (tid < o) { ss[tid] += ss[tid + o]; sq[tid] += sq[tid + o]; }
        __syncthreads();
    }
    if (tid == 0) {
        float mean = ss[0] * (1.f / 32768.f);
        float var  = sq[0] * (1.f / 32768.f) - mean * mean;
        float a = __ldg(gamma + ch) * rsqrtf(var + 1e-5f);
        g_a[ch] = a;
        g_bsh[ch] = __ldg(beta + ch) - mean * a;
    }
}

// ============ Kernel 4: normalize + ReLU ============
__global__ void __launch_bounds__(256) norm_kernel(float* __restrict__ out) {
    int i4 = blockIdx.x * 256 + threadIdx.x;
    int ch = (i4 >> 10) & 255;
    float a = g_a[ch], sh = g_bsh[ch];
    float4 v = ((const float4*)g_y)[i4];
    v.x = fmaxf(v.x * a + sh, 0.f);
    v.y = fmaxf(v.y * a + sh, 0.f);
    v.z = fmaxf(v.z * a + sh, 0.f);
    v.w = fmaxf(v.w * a + sh, 0.f);
    ((float4*)out)[i4] = v;
}

extern "C" void kernel_launch(void* const* d_in, const int* in_sizes, int n_in,
                              void* d_out, int out_size) {
    const float* x      = (const float*)d_in[0];
    const float* w_off  = (const float*)d_in[1];
    const float* b_off  = (const float*)d_in[2];
    const float* weight = (const float*)d_in[3];
    const float* bias   = (const float*)d_in[4];
    const float* gamma  = (const float*)d_in[5];
    const float* beta   = (const float*)d_in[6];
    float* out = (float*)d_out;

    static bool attr_set = false;
    if (!attr_set) {
        cudaFuncSetAttribute(deform_gemm_tc, cudaFuncAttributeMaxDynamicSharedMemorySize, SMEM_TC);
        attr_set = true;
    }

    offset_conv<<<512, 128>>>(x, w_off, b_off);
    convert_w<<<1152, 512>>>(weight);
    deform_gemm_tc<<<256, 512, SMEM_TC>>>(x, bias);
    stats_kernel<<<256, 256>>>(gamma, beta);
    norm_kernel<<<8192, 256>>>(out);
}

// round 15
// speedup vs baseline: 3.1334x; 1.0394x over previous
#include <cuda_runtime.h>
#include <cuda_fp16.h>
#include <cuda_bf16.h>
#include <cstdint>

typedef unsigned long long ull;
#define PLANE 4096
#define KTOT  2304

__device__ float g_om[2 * 8 * 27 * PLANE];   // [half][b][27][h][w] partial sums
__device__ float g_y [8 * 256 * PLANE];
__device__ float g_a [256];
__device__ float g_bsh[256];
__device__ __half g_wh[256 * KTOT];

__device__ __forceinline__ ull fma2(ull a, ull b, ull c) {
    ull d; asm("fma.rn.f32x2 %0, %1, %2, %3;" : "=l"(d) : "l"(a), "l"(b), "l"(c)); return d;
}
__device__ __forceinline__ ull pack2(float lo, float hi) {
    ull v; asm("mov.b64 %0, {%1, %2};" : "=l"(v) : "f"(lo), "f"(hi)); return v;
}
__device__ __forceinline__ float2 unpack2(ull v) {
    float2 f; asm("mov.b64 {%0, %1}, %2;" : "=f"(f.x), "=f"(f.y) : "l"(v)); return f;
}
__device__ __forceinline__ void mma16816(float* d, const uint32_t* a, const uint32_t* b) {
    asm volatile(
        "mma.sync.aligned.m16n8k16.row.col.f32.f16.f16.f32 "
        "{%0,%1,%2,%3}, {%4,%5,%6,%7}, {%8,%9}, {%0,%1,%2,%3};"
        : "+f"(d[0]), "+f"(d[1]), "+f"(d[2]), "+f"(d[3])
        : "r"(a[0]), "r"(a[1]), "r"(a[2]), "r"(a[3]), "r"(b[0]), "r"(b[1]));
}
__device__ __forceinline__ void ldsm_x4(uint32_t* r, uint32_t addr) {
    asm volatile("ldmatrix.sync.aligned.m8n8.x4.shared.b16 {%0,%1,%2,%3}, [%4];"
        : "=r"(r[0]), "=r"(r[1]), "=r"(r[2]), "=r"(r[3]) : "r"(addr));
}
__device__ __forceinline__ uint32_t smem_u32(const void* p) {
    uint32_t a;
    asm("{ .reg .u64 t; cvta.to.shared.u64 t, %1; cvt.u32.u64 %0, t; }" : "=r"(a) : "l"(p));
    return a;
}
__device__ __forceinline__ void cp16(uint32_t dst, const void* src) {
    asm volatile("cp.async.ca.shared.global [%0], [%1], 16;" :: "r"(dst), "l"(src));
}
#define CP_COMMIT() asm volatile("cp.async.commit_group;" ::: "memory")
#define CP_WAIT0()  asm volatile("cp.async.wait_group 0;" ::: "memory")

// ============ Kernel 1: offset conv (27ch 3x3), channel-split x2 ============
__global__ void __launch_bounds__(128) offset_conv(const float* __restrict__ x,
                                                   const float* __restrict__ woff,
                                                   const float* __restrict__ boff) {
    __shared__ float sw[27 * 32 * 12];
    const int tid = threadIdx.x;
    const int half = blockIdx.x >> 8;
    const int rest = blockIdx.x & 255;
    const int b = rest >> 5;
    const int h = ((rest & 31) << 1) + (tid >> 6);
    const int w = tid & 63;
    const int cbase = half << 7;

    ull acc2[27]; float acc1[27];
#pragma unroll
    for (int oc = 0; oc < 27; oc++) { acc2[oc] = 0ULL; acc1[oc] = 0.f; }

    for (int c0 = cbase; c0 < cbase + 128; c0 += 32) {
        __syncthreads();
        for (int i = tid; i < 27 * 32 * 9; i += 128) {
            int oc = i / 288, rem = i - oc * 288;
            int cl = rem / 9, j = rem - cl * 9;
            sw[(oc * 32 + cl) * 12 + j] = __ldg(&woff[(oc * 256 + c0 + cl) * 9 + j]);
        }
        __syncthreads();
        for (int cl = 0; cl < 32; cl++) {
            const float* xc = x + ((size_t)(b * 256 + c0 + cl) << 12);
            float v[9];
#pragma unroll
            for (int a = 0; a < 3; a++)
#pragma unroll
                for (int e = 0; e < 3; e++) {
                    int hh = h + a - 1, ww = w + e - 1;
                    bool ok = (hh >= 0) & (hh < 64) & (ww >= 0) & (ww < 64);
                    v[a * 3 + e] = ok ? __ldg(xc + hh * 64 + ww) : 0.f;
                }
            ull p0 = pack2(v[0], v[1]), p1 = pack2(v[2], v[3]);
            ull p2 = pack2(v[4], v[5]), p3 = pack2(v[6], v[7]);
            float v8 = v[8];
            const float* wb = sw + cl * 12;
#pragma unroll
            for (int oc = 0; oc < 27; oc++) {
                const float* wr = wb + oc * 384;
                ulonglong2 w01 = *(const ulonglong2*)(wr);
                ulonglong2 w23 = *(const ulonglong2*)(wr + 4);
                acc2[oc] = fma2(p0, w01.x, acc2[oc]);
                acc2[oc] = fma2(p1, w01.y, acc2[oc]);
                acc2[oc] = fma2(p2, w23.x, acc2[oc]);
                acc2[oc] = fma2(p3, w23.y, acc2[oc]);
                acc1[oc] = fmaf(v8, wr[8], acc1[oc]);
            }
        }
    }
    float* omh = g_om + (size_t)half * (8 * 27 * PLANE);
#pragma unroll
    for (int oc = 0; oc < 27; oc++) {
        float2 f = unpack2(acc2[oc]);
        float r = f.x + f.y + acc1[oc];
        if (half == 0) r += __ldg(boff + oc);
        omh[((size_t)(b * 27 + oc) << 12) + h * 64 + w] = r;
    }
}

// ============ Kernel 1b: weight -> fp16 (split into 2 launches) ============
__global__ void __launch_bounds__(512) convert_w(const float* __restrict__ weight, int base) {
    int i = base + blockIdx.x * 512 + threadIdx.x;
    g_wh[i] = __float2half_rn(__ldg(weight + i));
}

// ============ Kernel 2: deformable gather + fp16 mma.sync GEMM ============
// CTA per (b, h-pair): M=128 px, N=256 oc, K=2304 in 36 chunks of 64.
// ldmatrix operand fetch; double-buffered; one sync/chunk; B via cp.async.
#define APITCH_W 36
#define A_BYTES  18432                  // 128 * 144
#define B_BYTES  36864                  // 256 * 144
#define SM_AH    0                      // 2 x 18432
#define SM_B     36864                  // 2 x 36864
#define SM_COEF  110592                 // 1152 * 16
#define SM_IDX   129024                 // 1152 * 8
#define SMEM_TC  138240

__global__ void __launch_bounds__(512, 1) deform_gemm_tc(const float* __restrict__ x,
                                                         const float* __restrict__ bias) {
    extern __shared__ char smem[];
    const uint32_t smb = smem_u32(smem);
    const int tid = threadIdx.x;
    const int wid = tid >> 5;
    const int lane = tid & 31;
    const int b = blockIdx.x >> 5;
    const int h0 = (blockIdx.x & 31) << 1;

    float4*  coef4 = (float4*)(smem + SM_COEF);
    ushort4* idx4  = (ushort4*)(smem + SM_IDX);

    // ---- prologue: bilinear coefs per (tap, m); sums the two offset-conv halves
    for (int i = tid; i < 1152; i += 512) {
        int tap = i >> 7, m = i & 127;
        int r = m >> 6, px = m & 63;
        int h = h0 + r;
        const float* omb  = g_om + ((size_t)(b * 27) << 12) + h * 64 + px;
        const float* omb2 = omb + (size_t)(8 * 27 * PLANE);
        float offh = omb[(size_t)(2 * tap) << 12]     + omb2[(size_t)(2 * tap) << 12];
        float offw = omb[(size_t)(2 * tap + 1) << 12] + omb2[(size_t)(2 * tap + 1) << 12];
        float mv   = omb[(size_t)(18 + tap) << 12]    + omb2[(size_t)(18 + tap) << 12];
        float mask = 1.f / (1.f + __expf(-mv));
        int kh = tap / 3, kw = tap - kh * 3;
        float ph = (float)(h + kh - 1) + offh;
        float pw = (float)(px + kw - 1) + offw;
        float fh0 = floorf(ph), fw0 = floorf(pw);
        int hh0 = (int)fh0, ww0 = (int)fw0;
        float lh = ph - fh0, lw = pw - fw0;
        float hh = 1.f - lh, hw = 1.f - lw;
        bool vh0 = (hh0 >= 0) & (hh0 < 64), vh1 = (hh0 >= -1) & (hh0 < 63);
        bool vw0 = (ww0 >= 0) & (ww0 < 64), vw1 = (ww0 >= -1) & (ww0 < 63);
        int ch0 = min(max(hh0, 0), 63), ch1 = min(max(hh0 + 1, 0), 63);
        int cw0 = min(max(ww0, 0), 63), cw1 = min(max(ww0 + 1, 0), 63);
        float4 cf;
        cf.x = (vh0 & vw0) ? hh * hw * mask : 0.f;
        cf.y = (vh0 & vw1) ? hh * lw * mask : 0.f;
        cf.z = (vh1 & vw0) ? lh * hw * mask : 0.f;
        cf.w = (vh1 & vw1) ? lh * lw * mask : 0.f;
        coef4[i] = cf;
        ushort4 ix;
        ix.x = (unsigned short)(ch0 * 64 + cw0);
        ix.y = (unsigned short)(ch0 * 64 + cw1);
        ix.z = (unsigned short)(ch1 * 64 + cw0);
        ix.w = (unsigned short)(ch1 * 64 + cw1);
        idx4[i] = ix;
    }
    __syncthreads();   // tables are read cross-thread below

    const float* xb = x + ((size_t)(b * 256) << 12);
    const int m   = tid & 127;          // gather: M row owned
    const int kb0 = (tid >> 7) << 4;    // gather: k sub-range

    const int g = lane >> 2, t = lane & 3;
    const int wm = (wid & 3) << 5;      // warp M origin
    const int wn = (wid >> 2) << 6;     // warp N origin

    // ldmatrix per-lane address offsets (within a buffer)
    const uint32_t aoff = (uint32_t)((wm + (lane & 15)) * 144 + (lane >> 4) * 16);
    const uint32_t boff = (uint32_t)((wn + (lane & 7) + ((lane >> 4) << 3)) * 144
                                     + ((lane >> 3) & 1) * 16);

    float acc[2][8][4];
#pragma unroll
    for (int f = 0; f < 2; f++)
#pragma unroll
        for (int ni = 0; ni < 8; ni++)
#pragma unroll
            for (int e = 0; e < 4; e++) acc[f][ni][e] = 0.f;

#define STAGE_B(CC, BUF) do { \
        uint32_t bdst = smb + SM_B + (BUF) * B_BYTES; \
        _Pragma("unroll") \
        for (int i = 0; i < 4; i++) { \
            int lin = i * 512 + tid; \
            int oc = lin >> 3, j = lin & 7; \
            cp16(bdst + oc * 144 + j * 16, g_wh + (size_t)oc * KTOT + (CC) * 64 + j * 8); \
        } \
        CP_COMMIT(); \
    } while (0)

#define GATHER_A(CC, BUF) do { \
        char* ah_ = smem + SM_AH + (BUF) * A_BYTES; \
        int kg0 = (CC) * 64 + kb0; \
        int c_ = kg0 / 9; \
        int tap_ = kg0 - c_ * 9; \
        const float* pc_ = xb + ((size_t)c_ << 12); \
        int tofs_ = tap_ * 128 + m; \
        _Pragma("unroll") \
        for (int gseg = 0; gseg < 2; gseg++) { \
            unsigned short hb[8]; \
            _Pragma("unroll") \
            for (int jj = 0; jj < 8; jj++) { \
                float4  cf = coef4[tofs_]; \
                ushort4 ix = idx4[tofs_]; \
                float s = cf.x * __ldg(pc_ + ix.x) + cf.y * __ldg(pc_ + ix.y) \
                        + cf.z * __ldg(pc_ + ix.z) + cf.w * __ldg(pc_ + ix.w); \
                __half hi = __float2half_rn(s); \
                hb[jj] = *(unsigned short*)&hi; \
                tap_++; tofs_ += 128; \
                if (tap_ == 9) { tap_ = 0; tofs_ = m; pc_ += PLANE; } \
            } \
            int off = m * 144 + (kb0 + gseg * 8) * 2; \
            *(uint4*)(ah_ + off) = *(uint4*)hb; \
        } \
    } while (0)

    // prologue: stage chunk 0 into buffer 0
    STAGE_B(0, 0);
    GATHER_A(0, 0);
    CP_WAIT0();
    __syncthreads();

    for (int cc = 0; cc < 36; cc++) {
        const int buf = cc & 1;
        if (cc + 1 < 36) STAGE_B(cc + 1, buf ^ 1);

        const uint32_t abase = smb + SM_AH + buf * A_BYTES + aoff;
        const uint32_t bbase = smb + SM_B  + buf * B_BYTES + boff;

#pragma unroll
        for (int s = 0; s < 4; s++) {
            uint32_t a0[4], a1[4];
            ldsm_x4(a0, abase + s * 32);
            ldsm_x4(a1, abase + 2304 + s * 32);
#pragma unroll
            for (int np = 0; np < 4; np++) {
                uint32_t bq[4];
                ldsm_x4(bq, bbase + np * 2304 + s * 32);
                mma16816(acc[0][2 * np],     a0, bq);
                mma16816(acc[0][2 * np + 1], a0, bq + 2);
                mma16816(acc[1][2 * np],     a1, bq);
                mma16816(acc[1][2 * np + 1], a1, bq + 2);
            }
        }

        if (cc + 1 < 36) GATHER_A(cc + 1, buf ^ 1);
        CP_WAIT0();
        __syncthreads();
    }

    // ---- epilogue: d0=D[g][2t], d1=D[g][2t+1], d2=D[g+8][2t], d3=D[g+8][2t+1]
#pragma unroll
    for (int f = 0; f < 2; f++) {
        int m0 = wm + f * 16 + g;
        int m1 = m0 + 8;
        int p0 = (h0 + (m0 >> 6)) * 64 + (m0 & 63);
        int p1 = (h0 + (m1 >> 6)) * 64 + (m1 & 63);
#pragma unroll
        for (int ni = 0; ni < 8; ni++) {
            int oc = wn + ni * 8 + 2 * t;
            float b0 = __ldg(bias + oc), b1 = __ldg(bias + oc + 1);
            float* y0 = g_y + ((size_t)(b * 256 + oc) << 12);
            float* y1 = g_y + ((size_t)(b * 256 + oc + 1) << 12);
            y0[p0] = acc[f][ni][0] + b0;
            y1[p0] = acc[f][ni][1] + b1;
            y0[p1] = acc[f][ni][2] + b0;
            y1[p1] = acc[f][ni][3] + b1;
        }
    }
}

// ============ Kernel 3: per-channel mean/var -> scale/shift ============
__global__ void __launch_bounds__(256) stats_kernel(const float* __restrict__ gamma,
                                                    const float* __restrict__ beta) {
    __shared__ float ss[256], sq[256];
    const int ch = blockIdx.x, tid = threadIdx.x;
    float s = 0.f, q = 0.f;
    for (int b = 0; b < 8; b++) {
        const float4* y4 = (const float4*)(g_y + ((size_t)(b * 256 + ch) << 12));
#pragma unroll
        for (int r = 0; r < 4; r++) {
            float4 v = y4[r * 256 + tid];
            s += (v.x + v.y) + (v.z + v.w);
            q += v.x * v.x + v.y * v.y + v.z * v.z + v.w * v.w;
        }
    }
    ss[tid] = s; sq[tid] = q;
    __syncthreads();
    for (int o = 128; o > 0; o >>= 1) {
        if (tid < o) { ss[tid] += ss[tid + o]; sq[tid] += sq[tid + o]; }
        __syncthreads();
    }
    if (tid == 0) {
        float mean = ss[0] * (1.f / 32768.f);
        float var  = sq[0] * (1.f / 32768.f) - mean * mean;
        float a = __ldg(gamma + ch) * rsqrtf(var + 1e-5f);
        g_a[ch] = a;
        g_bsh[ch] = __ldg(beta + ch) - mean * a;
    }
}

// ============ Kernel 4: normalize + ReLU ============
__global__ void __launch_bounds__(256) norm_kernel(float* __restrict__ out) {
    int i4 = blockIdx.x * 256 + threadIdx.x;
    int ch = (i4 >> 10) & 255;
    float a = g_a[ch], sh = g_bsh[ch];
    float4 v = ((const float4*)g_y)[i4];
    v.x = fmaxf(v.x * a + sh, 0.f);
    v.y = fmaxf(v.y * a + sh, 0.f);
    v.z = fmaxf(v.z * a + sh, 0.f);
    v.w = fmaxf(v.w * a + sh, 0.f);
    ((float4*)out)[i4] = v;
}

extern "C" void kernel_launch(void* const* d_in, const int* in_sizes, int n_in,
                              void* d_out, int out_size) {
    const float* x      = (const float*)d_in[0];
    const float* w_off  = (const float*)d_in[1];
    const float* b_off  = (const float*)d_in[2];
    const float* weight = (const float*)d_in[3];
    const float* bias   = (const float*)d_in[4];
    const float* gamma  = (const float*)d_in[5];
    const float* beta   = (const float*)d_in[6];
    float* out = (float*)d_out;

    static bool attr_set = false;
    if (!attr_set) {
        cudaFuncSetAttribute(deform_gemm_tc, cudaFuncAttributeMaxDynamicSharedMemorySize, SMEM_TC);
        attr_set = true;
    }

    // launch order matters: ncu captures launch index 3 -> deform_gemm_tc
    offset_conv<<<512, 128>>>(x, w_off, b_off);
    convert_w<<<576, 512>>>(weight, 0);
    convert_w<<<576, 512>>>(weight, 294912);
    deform_gemm_tc<<<256, 512, SMEM_TC>>>(x, bias);
    stats_kernel<<<256, 256>>>(gamma, beta);
    norm_kernel<<<8192, 256>>>(out);
}

// round 16
// speedup vs baseline: 3.1468x; 1.0043x over previous
#include <cuda_runtime.h>
#include <cuda_fp16.h>
#include <cuda_bf16.h>
#include <cstdint>

typedef unsigned long long ull;
#define PLANE 4096
#define KTOT  2304

__device__ float g_om[2 * 8 * 27 * PLANE];   // [half][b][27][h][w] partial sums
__device__ float g_y [8 * 256 * PLANE];
__device__ float g_a [256];
__device__ float g_bsh[256];
__device__ __half g_wh[256 * KTOT];

__device__ __forceinline__ ull fma2(ull a, ull b, ull c) {
    ull d; asm("fma.rn.f32x2 %0, %1, %2, %3;" : "=l"(d) : "l"(a), "l"(b), "l"(c)); return d;
}
__device__ __forceinline__ ull pack2(float lo, float hi) {
    ull v; asm("mov.b64 %0, {%1, %2};" : "=l"(v) : "f"(lo), "f"(hi)); return v;
}
__device__ __forceinline__ float2 unpack2(ull v) {
    float2 f; asm("mov.b64 {%0, %1}, %2;" : "=f"(f.x), "=f"(f.y) : "l"(v)); return f;
}
__device__ __forceinline__ void mma16816(float* d, const uint32_t* a, const uint32_t* b) {
    asm volatile(
        "mma.sync.aligned.m16n8k16.row.col.f32.f16.f16.f32 "
        "{%0,%1,%2,%3}, {%4,%5,%6,%7}, {%8,%9}, {%0,%1,%2,%3};"
        : "+f"(d[0]), "+f"(d[1]), "+f"(d[2]), "+f"(d[3])
        : "r"(a[0]), "r"(a[1]), "r"(a[2]), "r"(a[3]), "r"(b[0]), "r"(b[1]));
}
__device__ __forceinline__ void ldsm_x4(uint32_t* r, uint32_t addr) {
    asm volatile("ldmatrix.sync.aligned.m8n8.x4.shared.b16 {%0,%1,%2,%3}, [%4];"
        : "=r"(r[0]), "=r"(r[1]), "=r"(r[2]), "=r"(r[3]) : "r"(addr));
}
__device__ __forceinline__ uint32_t smem_u32(const void* p) {
    uint32_t a;
    asm("{ .reg .u64 t; cvta.to.shared.u64 t, %1; cvt.u32.u64 %0, t; }" : "=r"(a) : "l"(p));
    return a;
}
__device__ __forceinline__ void cp16(uint32_t dst, const void* src) {
    asm volatile("cp.async.ca.shared.global [%0], [%1], 16;" :: "r"(dst), "l"(src));
}
#define CP_COMMIT() asm volatile("cp.async.commit_group;" ::: "memory")
#define CP_WAIT0()  asm volatile("cp.async.wait_group 0;" ::: "memory")

// ============ Kernel 1: offset conv (27ch 3x3), channel-split x2 ============
__global__ void __launch_bounds__(128) offset_conv(const float* __restrict__ x,
                                                   const float* __restrict__ woff,
                                                   const float* __restrict__ boff) {
    __shared__ float sw[27 * 32 * 12];
    const int tid = threadIdx.x;
    const int half = blockIdx.x >> 8;
    const int rest = blockIdx.x & 255;
    const int b = rest >> 5;
    const int h = ((rest & 31) << 1) + (tid >> 6);
    const int w = tid & 63;
    const int cbase = half << 7;

    ull acc2[27]; float acc1[27];
#pragma unroll
    for (int oc = 0; oc < 27; oc++) { acc2[oc] = 0ULL; acc1[oc] = 0.f; }

    for (int c0 = cbase; c0 < cbase + 128; c0 += 32) {
        __syncthreads();
        for (int i = tid; i < 27 * 32 * 9; i += 128) {
            int oc = i / 288, rem = i - oc * 288;
            int cl = rem / 9, j = rem - cl * 9;
            sw[(oc * 32 + cl) * 12 + j] = __ldg(&woff[(oc * 256 + c0 + cl) * 9 + j]);
        }
        __syncthreads();
        for (int cl = 0; cl < 32; cl++) {
            const float* xc = x + ((size_t)(b * 256 + c0 + cl) << 12);
            float v[9];
#pragma unroll
            for (int a = 0; a < 3; a++)
#pragma unroll
                for (int e = 0; e < 3; e++) {
                    int hh = h + a - 1, ww = w + e - 1;
                    bool ok = (hh >= 0) & (hh < 64) & (ww >= 0) & (ww < 64);
                    v[a * 3 + e] = ok ? __ldg(xc + hh * 64 + ww) : 0.f;
                }
            ull p0 = pack2(v[0], v[1]), p1 = pack2(v[2], v[3]);
            ull p2 = pack2(v[4], v[5]), p3 = pack2(v[6], v[7]);
            float v8 = v[8];
            const float* wb = sw + cl * 12;
#pragma unroll
            for (int oc = 0; oc < 27; oc++) {
                const float* wr = wb + oc * 384;
                ulonglong2 w01 = *(const ulonglong2*)(wr);
                ulonglong2 w23 = *(const ulonglong2*)(wr + 4);
                acc2[oc] = fma2(p0, w01.x, acc2[oc]);
                acc2[oc] = fma2(p1, w01.y, acc2[oc]);
                acc2[oc] = fma2(p2, w23.x, acc2[oc]);
                acc2[oc] = fma2(p3, w23.y, acc2[oc]);
                acc1[oc] = fmaf(v8, wr[8], acc1[oc]);
            }
        }
    }
    float* omh = g_om + (size_t)half * (8 * 27 * PLANE);
#pragma unroll
    for (int oc = 0; oc < 27; oc++) {
        float2 f = unpack2(acc2[oc]);
        float r = f.x + f.y + acc1[oc];
        if (half == 0) r += __ldg(boff + oc);
        omh[((size_t)(b * 27 + oc) << 12) + h * 64 + w] = r;
    }
}

// ============ Kernel 1b: weight -> fp16 (split into 2 launches) ============
__global__ void __launch_bounds__(512) convert_w(const float* __restrict__ weight, int base) {
    int i = base + blockIdx.x * 512 + threadIdx.x;
    g_wh[i] = __float2half_rn(__ldg(weight + i));
}

// ============ Kernel 2: deformable gather + fp16 mma.sync GEMM ============
// CTA per (b, h-pair): M=128 px, N=256 oc, K=2304 in 36 chunks of 64.
// Gather for chunk cc+1 interleaved into the MMA s-loop of chunk cc
// (4 samples per s-step; LDG latency hidden behind ldmatrix+HMMA issue).
#define APITCH_W 36
#define A_BYTES  18432                  // 128 * 144
#define B_BYTES  36864                  // 256 * 144
#define SM_AH    0                      // 2 x 18432
#define SM_B     36864                  // 2 x 36864
#define SM_COEF  110592                 // 1152 * 16
#define SM_IDX   129024                 // 1152 * 8
#define SMEM_TC  138240

__global__ void __launch_bounds__(512, 1) deform_gemm_tc(const float* __restrict__ x,
                                                         const float* __restrict__ bias) {
    extern __shared__ char smem[];
    const uint32_t smb = smem_u32(smem);
    const int tid = threadIdx.x;
    const int wid = tid >> 5;
    const int lane = tid & 31;
    const int b = blockIdx.x >> 5;
    const int h0 = (blockIdx.x & 31) << 1;

    float4*  coef4 = (float4*)(smem + SM_COEF);
    ushort4* idx4  = (ushort4*)(smem + SM_IDX);

    // ---- prologue: bilinear coefs per (tap, m); sums the two offset-conv halves
    for (int i = tid; i < 1152; i += 512) {
        int tap = i >> 7, m = i & 127;
        int r = m >> 6, px = m & 63;
        int h = h0 + r;
        const float* omb  = g_om + ((size_t)(b * 27) << 12) + h * 64 + px;
        const float* omb2 = omb + (size_t)(8 * 27 * PLANE);
        float offh = omb[(size_t)(2 * tap) << 12]     + omb2[(size_t)(2 * tap) << 12];
        float offw = omb[(size_t)(2 * tap + 1) << 12] + omb2[(size_t)(2 * tap + 1) << 12];
        float mv   = omb[(size_t)(18 + tap) << 12]    + omb2[(size_t)(18 + tap) << 12];
        float mask = 1.f / (1.f + __expf(-mv));
        int kh = tap / 3, kw = tap - kh * 3;
        float ph = (float)(h + kh - 1) + offh;
        float pw = (float)(px + kw - 1) + offw;
        float fh0 = floorf(ph), fw0 = floorf(pw);
        int hh0 = (int)fh0, ww0 = (int)fw0;
        float lh = ph - fh0, lw = pw - fw0;
        float hh = 1.f - lh, hw = 1.f - lw;
        bool vh0 = (hh0 >= 0) & (hh0 < 64), vh1 = (hh0 >= -1) & (hh0 < 63);
        bool vw0 = (ww0 >= 0) & (ww0 < 64), vw1 = (ww0 >= -1) & (ww0 < 63);
        int ch0 = min(max(hh0, 0), 63), ch1 = min(max(hh0 + 1, 0), 63);
        int cw0 = min(max(ww0, 0), 63), cw1 = min(max(ww0 + 1, 0), 63);
        float4 cf;
        cf.x = (vh0 & vw0) ? hh * hw * mask : 0.f;
        cf.y = (vh0 & vw1) ? hh * lw * mask : 0.f;
        cf.z = (vh1 & vw0) ? lh * hw * mask : 0.f;
        cf.w = (vh1 & vw1) ? lh * lw * mask : 0.f;
        coef4[i] = cf;
        ushort4 ix;
        ix.x = (unsigned short)(ch0 * 64 + cw0);
        ix.y = (unsigned short)(ch0 * 64 + cw1);
        ix.z = (unsigned short)(ch1 * 64 + cw0);
        ix.w = (unsigned short)(ch1 * 64 + cw1);
        idx4[i] = ix;
    }
    __syncthreads();   // tables are read cross-thread below

    const float* xb = x + ((size_t)(b * 256) << 12);
    const int m   = tid & 127;          // gather: M row owned
    const int kb0 = (tid >> 7) << 4;    // gather: k sub-range

    const int g = lane >> 2, t = lane & 3;
    const int wm = (wid & 3) << 5;      // warp M origin
    const int wn = (wid >> 2) << 6;     // warp N origin

    // ldmatrix per-lane address offsets (within a buffer)
    const uint32_t aoff = (uint32_t)((wm + (lane & 15)) * 144 + (lane >> 4) * 16);
    const uint32_t boff = (uint32_t)((wn + (lane & 7) + ((lane >> 4) << 3)) * 144
                                     + ((lane >> 3) & 1) * 16);

    float acc[2][8][4];
#pragma unroll
    for (int f = 0; f < 2; f++)
#pragma unroll
        for (int ni = 0; ni < 8; ni++)
#pragma unroll
            for (int e = 0; e < 4; e++) acc[f][ni][e] = 0.f;

#define STAGE_B(CC, BUF) do { \
        uint32_t bdst = smb + SM_B + (BUF) * B_BYTES; \
        _Pragma("unroll") \
        for (int i = 0; i < 4; i++) { \
            int lin = i * 512 + tid; \
            int oc = lin >> 3, j = lin & 7; \
            cp16(bdst + oc * 144 + j * 16, g_wh + (size_t)oc * KTOT + (CC) * 64 + j * 8); \
        } \
        CP_COMMIT(); \
    } while (0)

    // ---- prologue: gather chunk 0 + stage B chunk 0 into buffer 0
    STAGE_B(0, 0);
    {
        char* ah_ = smem + SM_AH;
        int c_ = kb0 / 9;
        int tap_ = kb0 - c_ * 9;
        const float* pc_ = xb + ((size_t)c_ << 12);
        int tofs_ = tap_ * 128 + m;
        unsigned short hb[16];
#pragma unroll
        for (int jj = 0; jj < 16; jj++) {
            float4  cf = coef4[tofs_];
            ushort4 ix = idx4[tofs_];
            float s = cf.x * __ldg(pc_ + ix.x) + cf.y * __ldg(pc_ + ix.y)
                    + cf.z * __ldg(pc_ + ix.z) + cf.w * __ldg(pc_ + ix.w);
            __half hi = __float2half_rn(s);
            hb[jj] = *(unsigned short*)&hi;
            tap_++; tofs_ += 128;
            if (tap_ == 9) { tap_ = 0; tofs_ = m; pc_ += PLANE; }
        }
        int off = m * 144 + kb0 * 2;
        *(uint4*)(ah_ + off)      = *(uint4*)hb;
        *(uint4*)(ah_ + off + 16) = *(uint4*)(hb + 8);
    }
    CP_WAIT0();
    __syncthreads();

    for (int cc = 0; cc < 36; cc++) {
        const int buf = cc & 1;
        const bool dog = (cc + 1 < 36);
        if (dog) STAGE_B(cc + 1, buf ^ 1);

        // gather cursor for chunk cc+1 (dummy re-gather of cc when last chunk)
        int kgN = (dog ? cc + 1 : cc) * 64 + kb0;
        int c_ = kgN / 9;
        int tap_ = kgN - c_ * 9;
        const float* pc_ = xb + ((size_t)c_ << 12);
        int tofs_ = tap_ * 128 + m;

        const uint32_t abase = smb + SM_AH + buf * A_BYTES + aoff;
        const uint32_t bbase = smb + SM_B  + buf * B_BYTES + boff;

        uint32_t hbw[8];

#pragma unroll
        for (int s = 0; s < 4; s++) {
            // ---- issue 4-sample gather (16 LDG); latency hidden by MMA below
            int tj[4]; ushort4 iv[4]; float cr[16];
#pragma unroll
            for (int j = 0; j < 4; j++) {
                tj[j] = tofs_;
                iv[j] = idx4[tofs_];
                cr[4 * j + 0] = __ldg(pc_ + iv[j].x);
                cr[4 * j + 1] = __ldg(pc_ + iv[j].y);
                cr[4 * j + 2] = __ldg(pc_ + iv[j].z);
                cr[4 * j + 3] = __ldg(pc_ + iv[j].w);
                tap_++; tofs_ += 128;
                if (tap_ == 9) { tap_ = 0; tofs_ = m; pc_ += PLANE; }
            }

            // ---- MMA step s of current chunk
            uint32_t a0[4], a1[4];
            ldsm_x4(a0, abase + s * 32);
            ldsm_x4(a1, abase + 2304 + s * 32);
#pragma unroll
            for (int np = 0; np < 4; np++) {
                uint32_t bq[4];
                ldsm_x4(bq, bbase + np * 2304 + s * 32);
                mma16816(acc[0][2 * np],     a0, bq);
                mma16816(acc[0][2 * np + 1], a0, bq + 2);
                mma16816(acc[1][2 * np],     a1, bq);
                mma16816(acc[1][2 * np + 1], a1, bq + 2);
            }

            // ---- convert the 4 samples (loads have landed by now)
#pragma unroll
            for (int jp = 0; jp < 2; jp++) {
                int j0 = 2 * jp, j1 = 2 * jp + 1;
                float4 c0 = coef4[tj[j0]], c1 = coef4[tj[j1]];
                float s0 = c0.x * cr[4 * j0] + c0.y * cr[4 * j0 + 1]
                         + c0.z * cr[4 * j0 + 2] + c0.w * cr[4 * j0 + 3];
                float s1 = c1.x * cr[4 * j1] + c1.y * cr[4 * j1 + 1]
                         + c1.z * cr[4 * j1 + 2] + c1.w * cr[4 * j1 + 3];
                __half2 hh = __floats2half2_rn(s0, s1);
                hbw[2 * s + jp] = *(uint32_t*)&hh;
            }
        }

        // ---- store gathered A for chunk cc+1 (contiguous 32B per thread)
        if (dog) {
            char* ah_ = smem + SM_AH + (buf ^ 1) * A_BYTES;
            int off = m * 144 + kb0 * 2;
            *(uint4*)(ah_ + off)      = make_uint4(hbw[0], hbw[1], hbw[2], hbw[3]);
            *(uint4*)(ah_ + off + 16) = make_uint4(hbw[4], hbw[5], hbw[6], hbw[7]);
        }
        CP_WAIT0();
        __syncthreads();
    }

    // ---- epilogue: d0=D[g][2t], d1=D[g][2t+1], d2=D[g+8][2t], d3=D[g+8][2t+1]
#pragma unroll
    for (int f = 0; f < 2; f++) {
        int m0 = wm + f * 16 + g;
        int m1 = m0 + 8;
        int p0 = (h0 + (m0 >> 6)) * 64 + (m0 & 63);
        int p1 = (h0 + (m1 >> 6)) * 64 + (m1 & 63);
#pragma unroll
        for (int ni = 0; ni < 8; ni++) {
            int oc = wn + ni * 8 + 2 * t;
            float b0 = __ldg(bias + oc), b1 = __ldg(bias + oc + 1);
            float* y0 = g_y + ((size_t)(b * 256 + oc) << 12);
            float* y1 = g_y + ((size_t)(b * 256 + oc + 1) << 12);
            y0[p0] = acc[f][ni][0] + b0;
            y1[p0] = acc[f][ni][1] + b1;
            y0[p1] = acc[f][ni][2] + b0;
            y1[p1] = acc[f][ni][3] + b1;
        }
    }
}

// ============ Kernel 3: per-channel mean/var -> scale/shift ============
__global__ void __launch_bounds__(256) stats_kernel(const float* __restrict__ gamma,
                                                    const float* __restrict__ beta) {
    __shared__ float ss[256], sq[256];
    const int ch = blockIdx.x, tid = threadIdx.x;
    float s = 0.f, q = 0.f;
    for (int b = 0; b < 8; b++) {
        const float4* y4 = (const float4*)(g_y + ((size_t)(b * 256 + ch) << 12));
#pragma unroll
        for (int r = 0; r < 4; r++) {
            float4 v = y4[r * 256 + tid];
            s += (v.x + v.y) + (v.z + v.w);
            q += v.x * v.x + v.y * v.y + v.z * v.z + v.w * v.w;
        }
    }
    ss[tid] = s; sq[tid] = q;
    __syncthreads();
    for (int o = 128; o > 0; o >>= 1) {
        if (tid < o) { ss[tid] += ss[tid + o]; sq[tid] += sq[tid + o]; }
        __syncthreads();
    }
    if (tid == 0) {
        float mean = ss[0] * (1.f / 32768.f);
        float var  = sq[0] * (1.f / 32768.f) - mean * mean;
        float a = __ldg(gamma + ch) * rsqrtf(var + 1e-5f);
        g_a[ch] = a;
        g_bsh[ch] = __ldg(beta + ch) - mean * a;
    }
}

// ============ Kernel 4: normalize + ReLU ============
__global__ void __launch_bounds__(256) norm_kernel(float* __restrict__ out) {
    int i4 = blockIdx.x * 256 + threadIdx.x;
    int ch = (i4 >> 10) & 255;
    float a = g_a[ch], sh = g_bsh[ch];
    float4 v = ((const float4*)g_y)[i4];
    v.x = fmaxf(v.x * a + sh, 0.f);
    v.y = fmaxf(v.y * a + sh, 0.f);
    v.z = fmaxf(v.z * a + sh, 0.f);
    v.w = fmaxf(v.w * a + sh, 0.f);
    ((float4*)out)[i4] = v;
}

extern "C" void kernel_launch(void* const* d_in, const int* in_sizes, int n_in,
                              void* d_out, int out_size) {
    const float* x      = (const float*)d_in[0];
    const float* w_off  = (const float*)d_in[1];
    const float* b_off  = (const float*)d_in[2];
    const float* weight = (const float*)d_in[3];
    const float* bias   = (const float*)d_in[4];
    const float* gamma  = (const float*)d_in[5];
    const float* beta   = (const float*)d_in[6];
    float* out = (float*)d_out;

    static bool attr_set = false;
    if (!attr_set) {
        cudaFuncSetAttribute(deform_gemm_tc, cudaFuncAttributeMaxDynamicSharedMemorySize, SMEM_TC);
        attr_set = true;
    }

    // launch order matters: ncu captures launch index 3 -> deform_gemm_tc
    offset_conv<<<512, 128>>>(x, w_off, b_off);
    convert_w<<<576, 512>>>(weight, 0);
    convert_w<<<576, 512>>>(weight, 294912);
    deform_gemm_tc<<<256, 512, SMEM_TC>>>(x, bias);
    stats_kernel<<<256, 256>>>(gamma, beta);
    norm_kernel<<<8192, 256>>>(out);
}

// round 17
// speedup vs baseline: 3.2789x; 1.0420x over previous
#include <cuda_runtime.h>
#include <cuda_fp16.h>
#include <cuda_bf16.h>
#include <cstdint>

typedef unsigned long long ull;
#define PLANE 4096
#define KTOT  2304

__device__ float g_om[2 * 8 * 27 * PLANE];   // [half][b][27][h][w] partial sums
__device__ float g_y [8 * 256 * PLANE];
__device__ float g_a [256];
__device__ float g_bsh[256];
__device__ __half g_wh[256 * KTOT];          // K reordered: k = tap*256 + c
__device__ float2 g_part[256 * 256];         // [ch][cta] partial (sum, sumsq)

__device__ __forceinline__ ull fma2(ull a, ull b, ull c) {
    ull d; asm("fma.rn.f32x2 %0, %1, %2, %3;" : "=l"(d) : "l"(a), "l"(b), "l"(c)); return d;
}
__device__ __forceinline__ ull pack2(float lo, float hi) {
    ull v; asm("mov.b64 %0, {%1, %2};" : "=l"(v) : "f"(lo), "f"(hi)); return v;
}
__device__ __forceinline__ float2 unpack2(ull v) {
    float2 f; asm("mov.b64 {%0, %1}, %2;" : "=f"(f.x), "=f"(f.y) : "l"(v)); return f;
}
__device__ __forceinline__ void mma16816(float* d, const uint32_t* a, const uint32_t* b) {
    asm volatile(
        "mma.sync.aligned.m16n8k16.row.col.f32.f16.f16.f32 "
        "{%0,%1,%2,%3}, {%4,%5,%6,%7}, {%8,%9}, {%0,%1,%2,%3};"
        : "+f"(d[0]), "+f"(d[1]), "+f"(d[2]), "+f"(d[3])
        : "r"(a[0]), "r"(a[1]), "r"(a[2]), "r"(a[3]), "r"(b[0]), "r"(b[1]));
}
__device__ __forceinline__ void ldsm_x4(uint32_t* r, uint32_t addr) {
    asm volatile("ldmatrix.sync.aligned.m8n8.x4.shared.b16 {%0,%1,%2,%3}, [%4];"
        : "=r"(r[0]), "=r"(r[1]), "=r"(r[2]), "=r"(r[3]) : "r"(addr));
}
__device__ __forceinline__ uint32_t smem_u32(const void* p) {
    uint32_t a;
    asm("{ .reg .u64 t; cvta.to.shared.u64 t, %1; cvt.u32.u64 %0, t; }" : "=r"(a) : "l"(p));
    return a;
}
__device__ __forceinline__ void cp16(uint32_t dst, const void* src) {
    asm volatile("cp.async.ca.shared.global [%0], [%1], 16;" :: "r"(dst), "l"(src));
}
#define CP_COMMIT() asm volatile("cp.async.commit_group;" ::: "memory")
#define CP_WAIT0()  asm volatile("cp.async.wait_group 0;" ::: "memory")

// ============ Kernel 1: offset conv (27ch 3x3), channel-split x2 ============
__global__ void __launch_bounds__(128) offset_conv(const float* __restrict__ x,
                                                   const float* __restrict__ woff,
                                                   const float* __restrict__ boff,
                                                   int half) {
    __shared__ float sw[27 * 32 * 12];
    const int tid = threadIdx.x;
    const int b = blockIdx.x >> 5;
    const int h = ((blockIdx.x & 31) << 1) + (tid >> 6);
    const int w = tid & 63;
    const int cbase = half << 7;

    ull acc2[27]; float acc1[27];
#pragma unroll
    for (int oc = 0; oc < 27; oc++) { acc2[oc] = 0ULL; acc1[oc] = 0.f; }

    for (int c0 = cbase; c0 < cbase + 128; c0 += 32) {
        __syncthreads();
        for (int i = tid; i < 27 * 32 * 9; i += 128) {
            int oc = i / 288, rem = i - oc * 288;
            int cl = rem / 9, j = rem - cl * 9;
            sw[(oc * 32 + cl) * 12 + j] = __ldg(&woff[(oc * 256 + c0 + cl) * 9 + j]);
        }
        __syncthreads();
        for (int cl = 0; cl < 32; cl++) {
            const float* xc = x + ((size_t)(b * 256 + c0 + cl) << 12);
            float v[9];
#pragma unroll
            for (int a = 0; a < 3; a++)
#pragma unroll
                for (int e = 0; e < 3; e++) {
                    int hh = h + a - 1, ww = w + e - 1;
                    bool ok = (hh >= 0) & (hh < 64) & (ww >= 0) & (ww < 64);
                    v[a * 3 + e] = ok ? __ldg(xc + hh * 64 + ww) : 0.f;
                }
            ull p0 = pack2(v[0], v[1]), p1 = pack2(v[2], v[3]);
            ull p2 = pack2(v[4], v[5]), p3 = pack2(v[6], v[7]);
            float v8 = v[8];
            const float* wb = sw + cl * 12;
#pragma unroll
            for (int oc = 0; oc < 27; oc++) {
                const float* wr = wb + oc * 384;
                ulonglong2 w01 = *(const ulonglong2*)(wr);
                ulonglong2 w23 = *(const ulonglong2*)(wr + 4);
                acc2[oc] = fma2(p0, w01.x, acc2[oc]);
                acc2[oc] = fma2(p1, w01.y, acc2[oc]);
                acc2[oc] = fma2(p2, w23.x, acc2[oc]);
                acc2[oc] = fma2(p3, w23.y, acc2[oc]);
                acc1[oc] = fmaf(v8, wr[8], acc1[oc]);
            }
        }
    }
    float* omh = g_om + (size_t)half * (8 * 27 * PLANE);
#pragma unroll
    for (int oc = 0; oc < 27; oc++) {
        float2 f = unpack2(acc2[oc]);
        float r = f.x + f.y + acc1[oc];
        if (half == 0) r += __ldg(boff + oc);
        omh[((size_t)(b * 27 + oc) << 12) + h * 64 + w] = r;
    }
}

// ============ Kernel 1b: weight -> fp16, K reordered tap-major ============
// g_wh[oc][tap*256 + c] = w[oc][c*9 + tap]
__global__ void __launch_bounds__(512) convert_w(const float* __restrict__ weight) {
    __shared__ float sw[KTOT];
    const int oc = blockIdx.x;
    const float* wrow = weight + (size_t)oc * KTOT;
    for (int i = threadIdx.x; i < KTOT; i += 512) sw[i] = __ldg(wrow + i);
    __syncthreads();
    __half* orow = g_wh + (size_t)oc * KTOT;
    for (int j = threadIdx.x; j < KTOT; j += 512) {
        int tap = j >> 8, c = j & 255;
        orow[j] = __float2half_rn(sw[c * 9 + tap]);
    }
}

// ============ Kernel 2: deformable gather + fp16 mma.sync GEMM ============
// K reordered tap-major: chunk cc covers ONE tap (tap=cc>>2), 64 channels.
// Gather for chunk cc+1 interleaved into MMA s-loop of chunk cc.
#define APITCH_W 36
#define A_BYTES  18432                  // 128 * 144
#define B_BYTES  36864                  // 256 * 144
#define SM_AH    0                      // 2 x 18432
#define SM_B     36864                  // 2 x 36864
#define SM_COEF  110592                 // 1152 * 16
#define SM_IDX   129024                 // 1152 * 8
#define SMEM_TC  138240

__global__ void __launch_bounds__(512, 1) deform_gemm_tc(const float* __restrict__ x,
                                                         const float* __restrict__ bias) {
    extern __shared__ char smem[];
    const uint32_t smb = smem_u32(smem);
    const int tid = threadIdx.x;
    const int wid = tid >> 5;
    const int lane = tid & 31;
    const int b = blockIdx.x >> 5;
    const int h0 = (blockIdx.x & 31) << 1;

    float4*  coef4 = (float4*)(smem + SM_COEF);
    ushort4* idx4  = (ushort4*)(smem + SM_IDX);

    // ---- prologue: bilinear coefs per (tap, m); sums the two offset-conv halves
    for (int i = tid; i < 1152; i += 512) {
        int tap = i >> 7, m = i & 127;
        int r = m >> 6, px = m & 63;
        int h = h0 + r;
        const float* omb  = g_om + ((size_t)(b * 27) << 12) + h * 64 + px;
        const float* omb2 = omb + (size_t)(8 * 27 * PLANE);
        float offh = omb[(size_t)(2 * tap) << 12]     + omb2[(size_t)(2 * tap) << 12];
        float offw = omb[(size_t)(2 * tap + 1) << 12] + omb2[(size_t)(2 * tap + 1) << 12];
        float mv   = omb[(size_t)(18 + tap) << 12]    + omb2[(size_t)(18 + tap) << 12];
        float mask = 1.f / (1.f + __expf(-mv));
        int kh = tap / 3, kw = tap - kh * 3;
        float ph = (float)(h + kh - 1) + offh;
        float pw = (float)(px + kw - 1) + offw;
        float fh0 = floorf(ph), fw0 = floorf(pw);
        int hh0 = (int)fh0, ww0 = (int)fw0;
        float lh = ph - fh0, lw = pw - fw0;
        float hh = 1.f - lh, hw = 1.f - lw;
        bool vh0 = (hh0 >= 0) & (hh0 < 64), vh1 = (hh0 >= -1) & (hh0 < 63);
        bool vw0 = (ww0 >= 0) & (ww0 < 64), vw1 = (ww0 >= -1) & (ww0 < 63);
        int ch0 = min(max(hh0, 0), 63), ch1 = min(max(hh0 + 1, 0), 63);
        int cw0 = min(max(ww0, 0), 63), cw1 = min(max(ww0 + 1, 0), 63);
        float4 cf;
        cf.x = (vh0 & vw0) ? hh * hw * mask : 0.f;
        cf.y = (vh0 & vw1) ? hh * lw * mask : 0.f;
        cf.z = (vh1 & vw0) ? lh * hw * mask : 0.f;
        cf.w = (vh1 & vw1) ? lh * lw * mask : 0.f;
        coef4[i] = cf;
        ushort4 ix;
        ix.x = (unsigned short)(ch0 * 64 + cw0);
        ix.y = (unsigned short)(ch0 * 64 + cw1);
        ix.z = (unsigned short)(ch1 * 64 + cw0);
        ix.w = (unsigned short)(ch1 * 64 + cw1);
        idx4[i] = ix;
    }
    __syncthreads();   // tables are read cross-thread below

    const float* xb = x + ((size_t)(b * 256) << 12);
    const int m   = tid & 127;          // gather: M row owned
    const int kb0 = (tid >> 7) << 4;    // gather: k sub-range (local 0..63)

    const int g = lane >> 2, t = lane & 3;
    const int wm = (wid & 3) << 5;      // warp M origin
    const int wn = (wid >> 2) << 6;     // warp N origin

    // ldmatrix per-lane address offsets (within a buffer)
    const uint32_t aoff = (uint32_t)((wm + (lane & 15)) * 144 + (lane >> 4) * 16);
    const uint32_t boff = (uint32_t)((wn + (lane & 7) + ((lane >> 4) << 3)) * 144
                                     + ((lane >> 3) & 1) * 16);

    float acc[2][8][4];
#pragma unroll
    for (int f = 0; f < 2; f++)
#pragma unroll
        for (int ni = 0; ni < 8; ni++)
#pragma unroll
            for (int e = 0; e < 4; e++) acc[f][ni][e] = 0.f;

#define STAGE_B(CC, BUF) do { \
        uint32_t bdst = smb + SM_B + (BUF) * B_BYTES; \
        _Pragma("unroll") \
        for (int i = 0; i < 4; i++) { \
            int lin = i * 512 + tid; \
            int oc = lin >> 3, j = lin & 7; \
            cp16(bdst + oc * 144 + j * 16, g_wh + (size_t)oc * KTOT + (CC) * 64 + j * 8); \
        } \
        CP_COMMIT(); \
    } while (0)

    // ---- prologue: gather chunk 0 (tap 0, channels kb0..kb0+15) + stage B
    STAGE_B(0, 0);
    {
        float4  cf = coef4[m];          // tap 0
        ushort4 iv = idx4[m];
        const float* pc = xb + ((size_t)kb0 << 12);
        unsigned short hb[16];
#pragma unroll
        for (int jj = 0; jj < 16; jj++) {
            float s = cf.x * __ldg(pc + iv.x) + cf.y * __ldg(pc + iv.y)
                    + cf.z * __ldg(pc + iv.z) + cf.w * __ldg(pc + iv.w);
            __half hi = __float2half_rn(s);
            hb[jj] = *(unsigned short*)&hi;
            pc += PLANE;
        }
        char* ah_ = smem + SM_AH;
        int off = m * 144 + kb0 * 2;
        *(uint4*)(ah_ + off)      = *(uint4*)hb;
        *(uint4*)(ah_ + off + 16) = *(uint4*)(hb + 8);
    }
    CP_WAIT0();
    __syncthreads();

    for (int cc = 0; cc < 36; cc++) {
        const int buf = cc & 1;
        const bool dog = (cc + 1 < 36);
        if (dog) STAGE_B(cc + 1, buf ^ 1);

        // gather setup for chunk cc+1 (single tap; dummy re-gather when last)
        const int ccn = dog ? cc + 1 : cc;
        const int tapN = ccn >> 2;
        const float4  cf = coef4[tapN * 128 + m];
        const ushort4 iv = idx4[tapN * 128 + m];
        const float* pc = xb + ((size_t)(((ccn & 3) << 6) + kb0) << 12);

        const uint32_t abase = smb + SM_AH + buf * A_BYTES + aoff;
        const uint32_t bbase = smb + SM_B  + buf * B_BYTES + boff;

        uint32_t hbw[8];

#pragma unroll
        for (int s = 0; s < 4; s++) {
            // ---- issue 4-sample gather (16 LDG); latency hidden by MMA below
            float cr[16];
#pragma unroll
            for (int j = 0; j < 4; j++) {
                cr[4 * j + 0] = __ldg(pc + iv.x);
                cr[4 * j + 1] = __ldg(pc + iv.y);
                cr[4 * j + 2] = __ldg(pc + iv.z);
                cr[4 * j + 3] = __ldg(pc + iv.w);
                pc += PLANE;
            }

            // ---- MMA step s of current chunk
            uint32_t a0[4], a1[4];
            ldsm_x4(a0, abase + s * 32);
            ldsm_x4(a1, abase + 2304 + s * 32);
#pragma unroll
            for (int np = 0; np < 4; np++) {
                uint32_t bq[4];
                ldsm_x4(bq, bbase + np * 2304 + s * 32);
                mma16816(acc[0][2 * np],     a0, bq);
                mma16816(acc[0][2 * np + 1], a0, bq + 2);
                mma16816(acc[1][2 * np],     a1, bq);
                mma16816(acc[1][2 * np + 1], a1, bq + 2);
            }

            // ---- convert the 4 samples (loads have landed by now)
#pragma unroll
            for (int jp = 0; jp < 2; jp++) {
                int j0 = 2 * jp, j1 = 2 * jp + 1;
                float s0 = cf.x * cr[4 * j0] + cf.y * cr[4 * j0 + 1]
                         + cf.z * cr[4 * j0 + 2] + cf.w * cr[4 * j0 + 3];
                float s1 = cf.x * cr[4 * j1] + cf.y * cr[4 * j1 + 1]
                         + cf.z * cr[4 * j1 + 2] + cf.w * cr[4 * j1 + 3];
                __half2 hh = __floats2half2_rn(s0, s1);
                hbw[2 * s + jp] = *(uint32_t*)&hh;
            }
        }

        // ---- store gathered A for chunk cc+1 (contiguous 32B per thread)
        if (dog) {
            char* ah_ = smem + SM_AH + (buf ^ 1) * A_BYTES;
            int off = m * 144 + kb0 * 2;
            *(uint4*)(ah_ + off)      = make_uint4(hbw[0], hbw[1], hbw[2], hbw[3]);
            *(uint4*)(ah_ + off + 16) = make_uint4(hbw[4], hbw[5], hbw[6], hbw[7]);
        }
        CP_WAIT0();
        __syncthreads();
    }

    // ---- epilogue: store y + accumulate per-channel BN partials
    float psum[16], psq[16];
#pragma unroll
    for (int i = 0; i < 16; i++) { psum[i] = 0.f; psq[i] = 0.f; }

#pragma unroll
    for (int f = 0; f < 2; f++) {
        int m0 = wm + f * 16 + g;
        int m1 = m0 + 8;
        int p0 = (h0 + (m0 >> 6)) * 64 + (m0 & 63);
        int p1 = (h0 + (m1 >> 6)) * 64 + (m1 & 63);
#pragma unroll
        for (int ni = 0; ni < 8; ni++) {
            int oc = wn + ni * 8 + 2 * t;
            float b0 = __ldg(bias + oc), b1 = __ldg(bias + oc + 1);
            float* y0 = g_y + ((size_t)(b * 256 + oc) << 12);
            float* y1 = g_y + ((size_t)(b * 256 + oc + 1) << 12);
            float v00 = acc[f][ni][0] + b0;
            float v01 = acc[f][ni][1] + b1;
            float v10 = acc[f][ni][2] + b0;
            float v11 = acc[f][ni][3] + b1;
            y0[p0] = v00; y1[p0] = v01; y0[p1] = v10; y1[p1] = v11;
            psum[ni * 2]     += v00 + v10;
            psum[ni * 2 + 1] += v01 + v11;
            psq[ni * 2]      += v00 * v00 + v10 * v10;
            psq[ni * 2 + 1]  += v01 * v01 + v11 * v11;
        }
    }
    // deterministic CTA reduce: 32 slots per channel (4 wm-warps x 8 g)
    {
        float* ssum = (float*)(smem);            // 256*32 floats = 32 KB
        float* ssq  = (float*)(smem + 32768);    // 32 KB
        int slot = ((wid & 3) << 3) + g;
#pragma unroll
        for (int ni = 0; ni < 8; ni++)
#pragma unroll
            for (int e1 = 0; e1 < 2; e1++) {
                int ch = wn + ni * 8 + 2 * t + e1;
                ssum[ch * 32 + slot] = psum[ni * 2 + e1];
                ssq [ch * 32 + slot] = psq [ni * 2 + e1];
            }
        __syncthreads();
        if (tid < 256) {
            float s = 0.f, q = 0.f;
#pragma unroll
            for (int k = 0; k < 32; k++) { s += ssum[tid * 32 + k]; q += ssq[tid * 32 + k]; }
            g_part[(size_t)tid * 256 + blockIdx.x] = make_float2(s, q);
        }
    }
}

// ============ Kernel 3: reduce partials -> scale/shift ============
__global__ void __launch_bounds__(256) stats_kernel(const float* __restrict__ gamma,
                                                    const float* __restrict__ beta) {
    __shared__ float ss[256], sq[256];
    const int ch = blockIdx.x, tid = threadIdx.x;
    float2 p = g_part[(size_t)ch * 256 + tid];
    ss[tid] = p.x; sq[tid] = p.y;
    __syncthreads();
    for (int o = 128; o > 0; o >>= 1) {
        if (tid < o) { ss[tid] += ss[tid + o]; sq[tid] += sq[tid + o]; }
        __syncthreads();
    }
    if (tid == 0) {
        float mean = ss[0] * (1.f / 32768.f);
        float var  = sq[0] * (1.f / 32768.f) - mean * mean;
        float a = __ldg(gamma + ch) * rsqrtf(var + 1e-5f);
        g_a[ch] = a;
        g_bsh[ch] = __ldg(beta + ch) - mean * a;
    }
}

// ============ Kernel 4: normalize + ReLU ============
__global__ void __launch_bounds__(256) norm_kernel(float* __restrict__ out) {
    int i4 = blockIdx.x * 256 + threadIdx.x;
    int ch = (i4 >> 10) & 255;
    float a = g_a[ch], sh = g_bsh[ch];
    float4 v = ((const float4*)g_y)[i4];
    v.x = fmaxf(v.x * a + sh, 0.f);
    v.y = fmaxf(v.y * a + sh, 0.f);
    v.z = fmaxf(v.z * a + sh, 0.f);
    v.w = fmaxf(v.w * a + sh, 0.f);
    ((float4*)out)[i4] = v;
}

extern "C" void kernel_launch(void* const* d_in, const int* in_sizes, int n_in,
                              void* d_out, int out_size) {
    const float* x      = (const float*)d_in[0];
    const float* w_off  = (const float*)d_in[1];
    const float* b_off  = (const float*)d_in[2];
    const float* weight = (const float*)d_in[3];
    const float* bias   = (const float*)d_in[4];
    const float* gamma  = (const float*)d_in[5];
    const float* beta   = (const float*)d_in[6];
    float* out = (float*)d_out;

    static bool attr_set = false;
    if (!attr_set) {
        cudaFuncSetAttribute(deform_gemm_tc, cudaFuncAttributeMaxDynamicSharedMemorySize, SMEM_TC);
        attr_set = true;
    }

    // launch order matters: ncu captures launch index 3 -> deform_gemm_tc
    offset_conv<<<256, 128>>>(x, w_off, b_off, 0);
    offset_conv<<<256, 128>>>(x, w_off, b_off, 1);
    convert_w<<<256, 512>>>(weight);
    deform_gemm_tc<<<256, 512, SMEM_TC>>>(x, bias);
    stats_kernel<<<256, 256>>>(gamma, beta);
    norm_kernel<<<8192, 256>>>(out);
}